// round 3
// baseline (speedup 1.0000x reference)
#include <cuda_runtime.h>
#include <math.h>

#define NN   100000
#define EE   3200000
#define FIN  512
#define HH   64
#define CC   40
#define KRANK 1600000u   // E - int(E*0.5): index into ascending sort

// ---------------- scratch (device globals; no allocation allowed) ----------
__device__ float    g_h[NN * HH];        // x @ w1
__device__ float    g_agg1[NN * HH];     // propagate(layer1), then relu'd h1 in-place
__device__ float    g_p[NN * CC];        // h1 @ w2
__device__ float    g_agg2[NN * CC];     // propagate(layer2)
__device__ float    g_x2[NN * CC];       // final logits (pre-log-softmax)
__device__ float    g_rn[NN];            // 1/max(||x2_i||, 1e-8)
__device__ float    g_dis[NN];           // deg^{-1/2}
__device__ int      g_deg[NN];
__device__ unsigned g_hist1[65536];
__device__ unsigned g_hist2[65536];
__device__ unsigned g_sel1[2];           // {hi bucket, residual rank}
__device__ float    g_thresh;
__device__ double   g_loss;

// ---------------- degree ---------------------------------------------------
__global__ void k_deg(const int* __restrict__ dst) {
    int e = blockIdx.x * blockDim.x + threadIdx.x;
    if (e < EE) atomicAdd(&g_deg[dst[e]], 1);
}

__global__ void k_dis() {
    int i = blockIdx.x * blockDim.x + threadIdx.x;
    if (i < NN) g_dis[i] = rsqrtf((float)g_deg[i] + 1.0f);
}

// ---------------- GEMM1: h = x[N,512] @ w1[512,64] -------------------------
#define BM 64
#define BN 64
#define BK 16
__global__ __launch_bounds__(256) void k_gemm1(const float* __restrict__ x,
                                               const float* __restrict__ w1) {
    __shared__ float As[BK][BM];
    __shared__ float Bs[BK][BN];
    int tid = threadIdx.x;
    int row0 = blockIdx.x * BM;
    int tx = tid % 16, ty = tid / 16;

    int ar = tid >> 2;          // 0..63 (tile row)
    int ak = (tid & 3) * 4;     // 0,4,8,12
    int bk = tid >> 4;          // 0..15
    int bc = (tid & 15) * 4;    // 0..60
    const bool rvalid = (row0 + ar) < NN;

    float acc[4][4];
#pragma unroll
    for (int i = 0; i < 4; i++)
#pragma unroll
        for (int j = 0; j < 4; j++) acc[i][j] = 0.f;

    for (int kt = 0; kt < FIN; kt += BK) {
        float4 a = rvalid ? *(const float4*)&x[(size_t)(row0 + ar) * FIN + kt + ak]
                          : make_float4(0.f, 0.f, 0.f, 0.f);
        As[ak + 0][ar] = a.x; As[ak + 1][ar] = a.y;
        As[ak + 2][ar] = a.z; As[ak + 3][ar] = a.w;
        *(float4*)&Bs[bk][bc] = *(const float4*)&w1[(size_t)(kt + bk) * HH + bc];
        __syncthreads();
#pragma unroll
        for (int k = 0; k < BK; k++) {
            float4 av = *(float4*)&As[k][ty * 4];
            float4 bv = *(float4*)&Bs[k][tx * 4];
            float aa[4] = {av.x, av.y, av.z, av.w};
            float bb[4] = {bv.x, bv.y, bv.z, bv.w};
#pragma unroll
            for (int i = 0; i < 4; i++)
#pragma unroll
                for (int j = 0; j < 4; j++) acc[i][j] += aa[i] * bb[j];
        }
        __syncthreads();
    }
#pragma unroll
    for (int i = 0; i < 4; i++) {
        int r = row0 + ty * 4 + i;
        if (r < NN) {
            float4 o = make_float4(acc[i][0], acc[i][1], acc[i][2], acc[i][3]);
            *(float4*)&g_h[(size_t)r * HH + tx * 4] = o;
        }
    }
}

// ---------------- scatter layer1: agg1[dst] += h[src]*norm ------------------
__global__ void k_scatter1(const int* __restrict__ src, const int* __restrict__ dst) {
    int t = blockIdx.x * blockDim.x + threadIdx.x;   // EE*16 threads
    int e = t >> 4;
    int c = t & 15;
    if (e >= EE) return;
    int s = src[e], d = dst[e];
    float nrm = g_dis[s] * g_dis[d];
    float4 v = *(const float4*)&g_h[(size_t)s * HH + c * 4];
    float* addr = &g_agg1[(size_t)d * HH + c * 4];
    asm volatile("red.global.add.v4.f32 [%0], {%1,%2,%3,%4};" ::
                 "l"(addr), "f"(v.x * nrm), "f"(v.y * nrm),
                 "f"(v.z * nrm), "f"(v.w * nrm) : "memory");
}

// ---------------- finish1: h1 = relu(agg1 + h*dis^2 + b1) (in place) --------
__global__ void k_finish1(const float* __restrict__ b1) {
    int i = blockIdx.x * blockDim.x + threadIdx.x;
    if (i < NN * HH) {
        int row = i >> 6, c = i & 63;
        float d = g_dis[row];
        float v = g_agg1[i] + g_h[i] * d * d + b1[c];
        g_agg1[i] = fmaxf(v, 0.f);
    }
}

// ---------------- GEMM2: p = h1[N,64] @ w2[64,40] ---------------------------
#define G2R 64
__global__ __launch_bounds__(256) void k_gemm2(const float* __restrict__ w2) {
    __shared__ float Ah[G2R][HH + 4];   // stride 68 floats keeps 16B alignment
    __shared__ float Ws[HH * CC];
    int tid = threadIdx.x;
    int row0 = blockIdx.x * G2R;
    for (int i = tid; i < HH * CC; i += 256) Ws[i] = w2[i];
    for (int i = tid; i < G2R * (HH / 4); i += 256) {
        int r = i >> 4, q = i & 15;
        float4 v = (row0 + r < NN) ? *(const float4*)&g_agg1[(size_t)(row0 + r) * HH + q * 4]
                                   : make_float4(0.f, 0.f, 0.f, 0.f);
        *(float4*)&Ah[r][q * 4] = v;
    }
    __syncthreads();
    for (int o = tid; o < G2R * CC; o += 256) {
        int r = o / CC, c = o - r * CC;
        float s = 0.f;
#pragma unroll 16
        for (int k = 0; k < HH; k++) s += Ah[r][k] * Ws[k * CC + c];
        if (row0 + r < NN) g_p[(size_t)(row0 + r) * CC + c] = s;
    }
}

// ---------------- scatter layer2: agg2[dst] += p[src]*norm ------------------
__global__ void k_scatter2(const int* __restrict__ src, const int* __restrict__ dst) {
    int t = blockIdx.x * blockDim.x + threadIdx.x;   // EE*10 threads
    if (t >= EE * 10) return;
    int e = t / 10;
    int c = t - e * 10;
    int s = src[e], d = dst[e];
    float nrm = g_dis[s] * g_dis[d];
    float4 v = *(const float4*)&g_p[(size_t)s * CC + c * 4];
    float* addr = &g_agg2[(size_t)d * CC + c * 4];
    asm volatile("red.global.add.v4.f32 [%0], {%1,%2,%3,%4};" ::
                 "l"(addr), "f"(v.x * nrm), "f"(v.y * nrm),
                 "f"(v.z * nrm), "f"(v.w * nrm) : "memory");
}

// ---------------- finish2: x2, rnorm, log_softmax (warp per row) ------------
__global__ void k_finish2(const float* __restrict__ b2, float* __restrict__ out) {
    int warp = (blockIdx.x * blockDim.x + threadIdx.x) >> 5;
    int lane = threadIdx.x & 31;
    if (warp >= NN) return;
    float d = g_dis[warp];
    float d2 = d * d;
    size_t base = (size_t)warp * CC;
    bool hb = lane < (CC - 32);
    float va = g_agg2[base + lane] + g_p[base + lane] * d2 + b2[lane];
    float vb = 0.f;
    if (hb) vb = g_agg2[base + 32 + lane] + g_p[base + 32 + lane] * d2 + b2[32 + lane];
    g_x2[base + lane] = va;
    if (hb) g_x2[base + 32 + lane] = vb;

    float sq = va * va + (hb ? vb * vb : 0.f);
#pragma unroll
    for (int o = 16; o; o >>= 1) sq += __shfl_xor_sync(0xffffffffu, sq, o);
    if (lane == 0) g_rn[warp] = 1.f / fmaxf(sqrtf(sq), 1e-8f);

    float mx = fmaxf(va, hb ? vb : -INFINITY);
#pragma unroll
    for (int o = 16; o; o >>= 1) mx = fmaxf(mx, __shfl_xor_sync(0xffffffffu, mx, o));
    float se = expf(va - mx) + (hb ? expf(vb - mx) : 0.f);
#pragma unroll
    for (int o = 16; o; o >>= 1) se += __shfl_xor_sync(0xffffffffu, se, o);
    float ls = logf(se);
    out[base + lane] = va - mx - ls;
    if (hb) out[base + 32 + lane] = vb - mx - ls;
}

// ---------------- exact rank-select of edge_weight (2-pass radix) -----------
__global__ void k_hist1(const float* __restrict__ ew) {
    int e = blockIdx.x * blockDim.x + threadIdx.x;
    if (e < EE) {
        unsigned u = __float_as_uint(ew[e]);   // positive floats: bit-monotone
        atomicAdd(&g_hist1[u >> 16], 1u);
    }
}

__global__ void k_sel1() {
    __shared__ unsigned part[256];
    __shared__ unsigned seg_s, rem_s;
    __shared__ unsigned s2[256];
    unsigned t = threadIdx.x;
    unsigned s = 0;
#pragma unroll 8
    for (int j = 0; j < 256; j++) s += g_hist1[t * 256 + j];
    part[t] = s;
    __syncthreads();
    if (t == 0) {
        unsigned k = KRANK, cum = 0;
        int sg = 0;
        for (; sg < 256; sg++) { if (cum + part[sg] > k) break; cum += part[sg]; }
        seg_s = sg; rem_s = k - cum;
    }
    __syncthreads();
    s2[t] = g_hist1[seg_s * 256 + t];
    __syncthreads();
    if (t == 0) {
        unsigned r = rem_s;
        int b = 0;
        for (; b < 256; b++) { if (r < s2[b]) break; r -= s2[b]; }
        g_sel1[0] = seg_s * 256 + b;
        g_sel1[1] = r;
    }
}

__global__ void k_hist2(const float* __restrict__ ew) {
    int e = blockIdx.x * blockDim.x + threadIdx.x;
    if (e < EE) {
        unsigned u = __float_as_uint(ew[e]);
        if ((u >> 16) == g_sel1[0]) atomicAdd(&g_hist2[u & 0xFFFFu], 1u);
    }
}

__global__ void k_sel2() {
    __shared__ unsigned part[256];
    __shared__ unsigned seg_s, rem_s;
    __shared__ unsigned s2[256];
    unsigned t = threadIdx.x;
    unsigned s = 0;
#pragma unroll 8
    for (int j = 0; j < 256; j++) s += g_hist2[t * 256 + j];
    part[t] = s;
    __syncthreads();
    if (t == 0) {
        unsigned k = g_sel1[1], cum = 0;
        int sg = 0;
        for (; sg < 256; sg++) { if (cum + part[sg] > k) break; cum += part[sg]; }
        seg_s = sg; rem_s = k - cum;
    }
    __syncthreads();
    s2[t] = g_hist2[seg_s * 256 + t];
    __syncthreads();
    if (t == 0) {
        unsigned r = rem_s;
        int b = 0;
        for (; b < 256; b++) { if (r < s2[b]) break; r -= s2[b]; }
        unsigned bits = (g_sel1[0] << 16) | (unsigned)(seg_s * 256 + b);
        g_thresh = __uint_as_float(bits);
    }
}

// ---------------- edge loss -------------------------------------------------
__global__ __launch_bounds__(256) void k_loss(const int* __restrict__ src,
                                              const int* __restrict__ dst,
                                              const float* __restrict__ ew,
                                              const float* __restrict__ lu) {
    __shared__ float red_s[8];
    int e = blockIdx.x * blockDim.x + threadIdx.x;
    float contrib = 0.f;
    if (e < EE) {
        int s = src[e], d = dst[e];
        const float4* A = (const float4*)&g_x2[(size_t)s * CC];
        const float4* B = (const float4*)&g_x2[(size_t)d * CC];
        float dot = 0.f;
#pragma unroll
        for (int q = 0; q < CC / 4; q++) {
            float4 a = A[q], b = B[q];
            dot += a.x * b.x + a.y * b.y + a.z * b.z + a.w * b.w;
        }
        float cosv = dot * g_rn[s] * g_rn[d];
        float w = ew[e];
        bool m = (w >= g_thresh);
        float cs = 1.f - cosv;          // cosine_sim
        float lp = m ? cs : (1.f - cs); // where(mask, 1-cos, cos)
        float le = m ? w : (1.f - w);
        contrib = le * lp * lu[e];
    }
#pragma unroll
    for (int o = 16; o; o >>= 1) contrib += __shfl_xor_sync(0xffffffffu, contrib, o);
    int lane = threadIdx.x & 31, wid = threadIdx.x >> 5;
    if (lane == 0) red_s[wid] = contrib;
    __syncthreads();
    if (wid == 0) {
        float v = (lane < 8) ? red_s[lane] : 0.f;
#pragma unroll
        for (int o = 4; o; o >>= 1) v += __shfl_xor_sync(0xffffffffu, v, o);
        if (lane == 0) atomicAdd(&g_loss, (double)v);
    }
}

__global__ void k_out_loss(float* out, int out_size) {
    if (out_size > NN * CC) out[out_size - 1] = (float)(g_loss / (double)EE);
}

// ---------------- launch ----------------------------------------------------
extern "C" void kernel_launch(void* const* d_in, const int* in_sizes, int n_in,
                              void* d_out, int out_size) {
    const float* x  = (const float*)d_in[0];
    const int*   ei = (const int*)d_in[1];
    const float* ew = (const float*)d_in[2];
    const float* lu = (const float*)d_in[3];
    const float* w1 = (const float*)d_in[4];
    const float* b1 = (const float*)d_in[5];
    const float* w2 = (const float*)d_in[6];
    const float* b2 = (const float*)d_in[7];
    float* out = (float*)d_out;

    const int* src = ei;
    const int* dst = ei + EE;

    void *p_agg1, *p_agg2, *p_deg, *p_h1, *p_h2, *p_loss;
    cudaGetSymbolAddress(&p_agg1, g_agg1);
    cudaGetSymbolAddress(&p_agg2, g_agg2);
    cudaGetSymbolAddress(&p_deg,  g_deg);
    cudaGetSymbolAddress(&p_h1,   g_hist1);
    cudaGetSymbolAddress(&p_h2,   g_hist2);
    cudaGetSymbolAddress(&p_loss, g_loss);

    cudaMemsetAsync(p_agg1, 0, sizeof(g_agg1));
    cudaMemsetAsync(p_agg2, 0, sizeof(g_agg2));
    cudaMemsetAsync(p_deg,  0, sizeof(g_deg));
    cudaMemsetAsync(p_h1,   0, sizeof(g_hist1));
    cudaMemsetAsync(p_h2,   0, sizeof(g_hist2));
    cudaMemsetAsync(p_loss, 0, sizeof(g_loss));

    k_deg<<<(EE + 255) / 256, 256>>>(dst);
    k_dis<<<(NN + 255) / 256, 256>>>();
    k_gemm1<<<(NN + BM - 1) / BM, 256>>>(x, w1);
    k_scatter1<<<(EE * 16 + 255) / 256, 256>>>(src, dst);
    k_finish1<<<(NN * HH + 255) / 256, 256>>>(b1);
    k_gemm2<<<(NN + G2R - 1) / G2R, 256>>>(w2);
    k_scatter2<<<(EE * 10 + 255) / 256, 256>>>(src, dst);
    k_finish2<<<(NN * 32 + 255) / 256, 256>>>(b2, out);

    k_hist1<<<(EE + 255) / 256, 256>>>(ew);
    k_sel1<<<1, 256>>>();
    k_hist2<<<(EE + 255) / 256, 256>>>(ew);
    k_sel2<<<1, 256>>>();

    k_loss<<<(EE + 255) / 256, 256>>>(src, dst, ew, lu);
    k_out_loss<<<1, 1>>>(out, out_size);
}

// round 6
// speedup vs baseline: 1.7649x; 1.7649x over previous
#include <cuda_runtime.h>
#include <math.h>

#define NN   100000
#define EE   3200000
#define FIN  512
#define HH   64
#define CC   40
#define KRANK 1600000u   // E - int(E*0.5): index into ascending sort

// ---------------- scratch (device globals; no allocation allowed) ----------
__device__ float    g_h[NN * HH];        // hs = (x @ w1) * dis[row]
__device__ float    g_h1[NN * HH];       // relu'd hidden layer
__device__ float    g_p[NN * CC];        // ps = (h1 @ w2) * dis[row]
__device__ float    g_x2[NN * CC];       // final logits (pre-log-softmax)
__device__ float    g_rn[NN];            // 1/max(||x2_i||, 1e-8)
__device__ float    g_dis[NN];           // (deg+1)^{-1/2}
__device__ int      g_deg[NN];
__device__ int      g_off[NN + 1];       // CSR row offsets (by dst)
__device__ int      g_cur[NN];           // fill cursors
__device__ int      g_csr[EE];           // src ids grouped by dst
__device__ unsigned g_hist1[65536];
__device__ unsigned g_hist2[65536];
__device__ unsigned g_sel1[2];           // {hi bucket, residual rank}
__device__ float    g_thresh;
__device__ double   g_loss;

// ---------------- degree ---------------------------------------------------
__global__ void k_deg(const int* __restrict__ dst) {
    int e = blockIdx.x * blockDim.x + threadIdx.x;
    if (e < EE) atomicAdd(&g_deg[dst[e]], 1);
}

__global__ void k_dis() {
    int i = blockIdx.x * blockDim.x + threadIdx.x;
    if (i < NN) g_dis[i] = rsqrtf((float)g_deg[i] + 1.0f);
}

// ---------------- exclusive scan of deg -> off, cur (single block) ---------
__global__ __launch_bounds__(1024) void k_scan() {
    const int CH = (NN + 1023) / 1024;  // 98
    int t = threadIdx.x;
    int start = t * CH;
    int end = min(start + CH, NN);
    int s = 0;
    for (int i = start; i < end; i++) s += g_deg[i];

    __shared__ int wsum[32];
    int lane = t & 31, wid = t >> 5;
    int v = s;
#pragma unroll
    for (int o = 1; o < 32; o <<= 1) {
        int u = __shfl_up_sync(0xffffffffu, v, o);
        if (lane >= o) v += u;
    }
    if (lane == 31) wsum[wid] = v;
    __syncthreads();
    if (wid == 0) {
        int w = wsum[lane];
#pragma unroll
        for (int o = 1; o < 32; o <<= 1) {
            int u = __shfl_up_sync(0xffffffffu, w, o);
            if (lane >= o) w += u;
        }
        wsum[lane] = w;
    }
    __syncthreads();
    int base = v - s + (wid > 0 ? wsum[wid - 1] : 0);
    int run = base;
    for (int i = start; i < end; i++) {
        g_off[i] = run;
        g_cur[i] = run;
        run += g_deg[i];
    }
    if (start < NN && end == NN) g_off[NN] = run;
}

// ---------------- CSR fill ---------------------------------------------------
__global__ void k_fill(const int* __restrict__ src, const int* __restrict__ dst) {
    int e = blockIdx.x * blockDim.x + threadIdx.x;
    if (e < EE) {
        int pos = atomicAdd(&g_cur[dst[e]], 1);
        g_csr[pos] = src[e];
    }
}

// ---------------- GEMM1: hs = (x[N,512] @ w1[512,64]) * dis ----------------
#define BM 128
#define BN 64
#define BK 16
__global__ __launch_bounds__(256) void k_gemm1(const float* __restrict__ x,
                                               const float* __restrict__ w1) {
    __shared__ float As[2][BK][BM];
    __shared__ float Bs[2][BK][BN];
    int tid = threadIdx.x;
    int row0 = blockIdx.x * BM;

    int ar = tid >> 1, ak = (tid & 1) * 8;          // A: 8 floats/thread
    int bk = tid >> 4, bc = (tid & 15) * 4;         // B: 4 floats/thread
    int ty = tid >> 4, tx = tid & 15;               // 8x4 micro-tile
    const bool rv = (row0 + ar) < NN;
    const float* xr = x + (size_t)(row0 + ar) * FIN + ak;

    float acc[8][4];
#pragma unroll
    for (int i = 0; i < 8; i++)
#pragma unroll
        for (int j = 0; j < 4; j++) acc[i][j] = 0.f;

    float4 a0 = rv ? *(const float4*)(xr + 0) : make_float4(0, 0, 0, 0);
    float4 a1 = rv ? *(const float4*)(xr + 4) : make_float4(0, 0, 0, 0);
    float4 bb = *(const float4*)&w1[(size_t)bk * HH + bc];

    int buf = 0;
    for (int kt = 0; kt < FIN; kt += BK) {
        As[buf][ak + 0][ar] = a0.x; As[buf][ak + 1][ar] = a0.y;
        As[buf][ak + 2][ar] = a0.z; As[buf][ak + 3][ar] = a0.w;
        As[buf][ak + 4][ar] = a1.x; As[buf][ak + 5][ar] = a1.y;
        As[buf][ak + 6][ar] = a1.z; As[buf][ak + 7][ar] = a1.w;
        *(float4*)&Bs[buf][bk][bc] = bb;
        __syncthreads();

        if (kt + BK < FIN) {
            a0 = rv ? *(const float4*)(xr + kt + BK)     : make_float4(0, 0, 0, 0);
            a1 = rv ? *(const float4*)(xr + kt + BK + 4) : make_float4(0, 0, 0, 0);
            bb = *(const float4*)&w1[(size_t)(kt + BK + bk) * HH + bc];
        }
#pragma unroll
        for (int k = 0; k < BK; k++) {
            float4 A0 = *(float4*)&As[buf][k][ty * 8];
            float4 A1 = *(float4*)&As[buf][k][ty * 8 + 4];
            float4 B  = *(float4*)&Bs[buf][k][tx * 4];
            float aa[8] = {A0.x, A0.y, A0.z, A0.w, A1.x, A1.y, A1.z, A1.w};
            float bv[4] = {B.x, B.y, B.z, B.w};
#pragma unroll
            for (int i = 0; i < 8; i++)
#pragma unroll
                for (int j = 0; j < 4; j++) acc[i][j] += aa[i] * bv[j];
        }
        buf ^= 1;
    }
#pragma unroll
    for (int i = 0; i < 8; i++) {
        int r = row0 + ty * 8 + i;
        if (r < NN) {
            float dd = g_dis[r];
            float4 o = make_float4(acc[i][0] * dd, acc[i][1] * dd,
                                   acc[i][2] * dd, acc[i][3] * dd);
            *(float4*)&g_h[(size_t)r * HH + tx * 4] = o;
        }
    }
}

// ---------------- gather layer1 + relu/bias (warp per node) -----------------
__global__ __launch_bounds__(256) void k_gather1(const float* __restrict__ b1) {
    int n = blockIdx.x * 8 + (threadIdx.x >> 5);
    if (n >= NN) return;
    int lane = threadIdx.x & 31;
    const float2* hs2 = (const float2*)g_h;
    float2 acc = hs2[(size_t)n * 32 + lane];            // self-loop term (hs[n])
    int beg = g_off[n], end = g_off[n + 1];
#pragma unroll 4
    for (int i = beg; i < end; i++) {
        int s = __ldg(&g_csr[i]);                       // uniform across warp
        float2 v = __ldg(&hs2[(size_t)s * 32 + lane]);
        acc.x += v.x; acc.y += v.y;
    }
    float d = g_dis[n];
    float2 bv = ((const float2*)b1)[lane];
    float2 o;
    o.x = fmaxf(acc.x * d + bv.x, 0.f);
    o.y = fmaxf(acc.y * d + bv.y, 0.f);
    ((float2*)g_h1)[(size_t)n * 32 + lane] = o;
}

// ---------------- GEMM2: ps = (h1[N,64] @ w2[64,40]) * dis ------------------
#define G2R 64
__global__ __launch_bounds__(256) void k_gemm2(const float* __restrict__ w2) {
    __shared__ float Ah[G2R][HH + 4];   // stride 68 floats: 272B, 16B-aligned rows
    __shared__ float Ws[HH * CC];
    int tid = threadIdx.x;
    int row0 = blockIdx.x * G2R;
    for (int i = tid; i < HH * CC; i += 256) Ws[i] = w2[i];
    for (int i = tid; i < G2R * (HH / 4); i += 256) {
        int r = i >> 4, q = i & 15;
        float4 v = (row0 + r < NN) ? *(const float4*)&g_h1[(size_t)(row0 + r) * HH + q * 4]
                                   : make_float4(0.f, 0.f, 0.f, 0.f);
        *(float4*)&Ah[r][q * 4] = v;
    }
    __syncthreads();
    for (int o = tid; o < G2R * CC; o += 256) {
        int r = o / CC, c = o - r * CC;
        float s = 0.f;
#pragma unroll 16
        for (int k = 0; k < HH; k++) s += Ah[r][k] * Ws[k * CC + c];
        int row = row0 + r;
        if (row < NN) g_p[(size_t)row * CC + c] = s * g_dis[row];
    }
}

// ---- gather layer2 + bias + x2 + rnorm + log_softmax (warp per node) -------
__global__ __launch_bounds__(256) void k_gather2(const float* __restrict__ b2,
                                                 float* __restrict__ out) {
    int n = blockIdx.x * 8 + (threadIdx.x >> 5);
    if (n >= NN) return;
    int lane = threadIdx.x & 31;
    bool hb = lane < (CC - 32);
    size_t base = (size_t)n * CC;
    float va = g_p[base + lane];                        // self-loop (ps[n])
    float vb = hb ? g_p[base + 32 + lane] : 0.f;
    int beg = g_off[n], end = g_off[n + 1];
#pragma unroll 4
    for (int i = beg; i < end; i++) {
        int s = __ldg(&g_csr[i]);
        size_t sb = (size_t)s * CC;
        va += __ldg(&g_p[sb + lane]);
        if (hb) vb += __ldg(&g_p[sb + 32 + lane]);
    }
    float d = g_dis[n];
    float xa = va * d + b2[lane];
    float xb = hb ? vb * d + b2[32 + lane] : 0.f;
    g_x2[base + lane] = xa;
    if (hb) g_x2[base + 32 + lane] = xb;

    float sq = xa * xa + (hb ? xb * xb : 0.f);
#pragma unroll
    for (int o = 16; o; o >>= 1) sq += __shfl_xor_sync(0xffffffffu, sq, o);
    if (lane == 0) g_rn[n] = 1.f / fmaxf(sqrtf(sq), 1e-8f);

    float mx = fmaxf(xa, hb ? xb : -1e30f);
#pragma unroll
    for (int o = 16; o; o >>= 1) mx = fmaxf(mx, __shfl_xor_sync(0xffffffffu, mx, o));
    float se = expf(xa - mx) + (hb ? expf(xb - mx) : 0.f);
#pragma unroll
    for (int o = 16; o; o >>= 1) se += __shfl_xor_sync(0xffffffffu, se, o);
    float ls = logf(se);
    out[base + lane] = xa - mx - ls;
    if (hb) out[base + 32 + lane] = xb - mx - ls;
}

// ---------------- exact rank-select of edge_weight (2-pass radix) -----------
__global__ void k_hist1(const float* __restrict__ ew) {
    int e = blockIdx.x * blockDim.x + threadIdx.x;
    if (e < EE) {
        unsigned u = __float_as_uint(ew[e]);   // positive floats: bit-monotone
        atomicAdd(&g_hist1[u >> 16], 1u);
    }
}

__global__ void k_sel1() {
    __shared__ unsigned part[256];
    __shared__ unsigned seg_s, rem_s;
    __shared__ unsigned s2[256];
    unsigned t = threadIdx.x;
    unsigned s = 0;
#pragma unroll 8
    for (int j = 0; j < 256; j++) s += g_hist1[t * 256 + j];
    part[t] = s;
    __syncthreads();
    if (t == 0) {
        unsigned k = KRANK, cum = 0;
        int sg = 0;
        for (; sg < 256; sg++) { if (cum + part[sg] > k) break; cum += part[sg]; }
        seg_s = sg; rem_s = k - cum;
    }
    __syncthreads();
    s2[t] = g_hist1[seg_s * 256 + t];
    __syncthreads();
    if (t == 0) {
        unsigned r = rem_s;
        int b = 0;
        for (; b < 256; b++) { if (r < s2[b]) break; r -= s2[b]; }
        g_sel1[0] = seg_s * 256 + b;
        g_sel1[1] = r;
    }
}

__global__ void k_hist2(const float* __restrict__ ew) {
    int e = blockIdx.x * blockDim.x + threadIdx.x;
    if (e < EE) {
        unsigned u = __float_as_uint(ew[e]);
        if ((u >> 16) == g_sel1[0]) atomicAdd(&g_hist2[u & 0xFFFFu], 1u);
    }
}

__global__ void k_sel2() {
    __shared__ unsigned part[256];
    __shared__ unsigned seg_s, rem_s;
    __shared__ unsigned s2[256];
    unsigned t = threadIdx.x;
    unsigned s = 0;
#pragma unroll 8
    for (int j = 0; j < 256; j++) s += g_hist2[t * 256 + j];
    part[t] = s;
    __syncthreads();
    if (t == 0) {
        unsigned k = g_sel1[1], cum = 0;
        int sg = 0;
        for (; sg < 256; sg++) { if (cum + part[sg] > k) break; cum += part[sg]; }
        seg_s = sg; rem_s = k - cum;
    }
    __syncthreads();
    s2[t] = g_hist2[seg_s * 256 + t];
    __syncthreads();
    if (t == 0) {
        unsigned r = rem_s;
        int b = 0;
        for (; b < 256; b++) { if (r < s2[b]) break; r -= s2[b]; }
        unsigned bits = (g_sel1[0] << 16) | (unsigned)(seg_s * 256 + b);
        g_thresh = __uint_as_float(bits);
    }
}

// ---------------- edge loss -------------------------------------------------
__global__ __launch_bounds__(256) void k_loss(const int* __restrict__ src,
                                              const int* __restrict__ dst,
                                              const float* __restrict__ ew,
                                              const float* __restrict__ lu) {
    __shared__ float red_s[8];
    int e = blockIdx.x * blockDim.x + threadIdx.x;
    float contrib = 0.f;
    if (e < EE) {
        int s = src[e], d = dst[e];
        const float4* A = (const float4*)&g_x2[(size_t)s * CC];
        const float4* B = (const float4*)&g_x2[(size_t)d * CC];
        float dot = 0.f;
#pragma unroll
        for (int q = 0; q < CC / 4; q++) {
            float4 a = A[q], b = B[q];
            dot += a.x * b.x + a.y * b.y + a.z * b.z + a.w * b.w;
        }
        float cosv = dot * g_rn[s] * g_rn[d];
        float w = ew[e];
        bool m = (w >= g_thresh);
        float cs = 1.f - cosv;          // cosine_sim
        float lp = m ? cs : (1.f - cs); // where(mask, 1-cos, cos)
        float le = m ? w : (1.f - w);
        contrib = le * lp * lu[e];
    }
#pragma unroll
    for (int o = 16; o; o >>= 1) contrib += __shfl_xor_sync(0xffffffffu, contrib, o);
    int lane = threadIdx.x & 31, wid = threadIdx.x >> 5;
    if (lane == 0) red_s[wid] = contrib;
    __syncthreads();
    if (wid == 0) {
        float v = (lane < 8) ? red_s[lane] : 0.f;
#pragma unroll
        for (int o = 4; o; o >>= 1) v += __shfl_xor_sync(0xffffffffu, v, o);
        if (lane == 0) atomicAdd(&g_loss, (double)v);
    }
}

__global__ void k_out_loss(float* out, int out_size) {
    if (out_size > NN * CC) out[out_size - 1] = (float)(g_loss / (double)EE);
}

// ---------------- launch ----------------------------------------------------
extern "C" void kernel_launch(void* const* d_in, const int* in_sizes, int n_in,
                              void* d_out, int out_size) {
    const float* x  = (const float*)d_in[0];
    const int*   ei = (const int*)d_in[1];
    const float* ew = (const float*)d_in[2];
    const float* lu = (const float*)d_in[3];
    const float* w1 = (const float*)d_in[4];
    const float* b1 = (const float*)d_in[5];
    const float* w2 = (const float*)d_in[6];
    const float* b2 = (const float*)d_in[7];
    float* out = (float*)d_out;

    const int* src = ei;
    const int* dst = ei + EE;

    void *p_deg, *p_h1, *p_h2, *p_loss;
    cudaGetSymbolAddress(&p_deg,  g_deg);
    cudaGetSymbolAddress(&p_h1,   g_hist1);
    cudaGetSymbolAddress(&p_h2,   g_hist2);
    cudaGetSymbolAddress(&p_loss, g_loss);

    cudaMemsetAsync(p_deg,  0, sizeof(g_deg));
    cudaMemsetAsync(p_h1,   0, sizeof(g_hist1));
    cudaMemsetAsync(p_h2,   0, sizeof(g_hist2));
    cudaMemsetAsync(p_loss, 0, sizeof(g_loss));

    k_deg<<<(EE + 255) / 256, 256>>>(dst);
    k_dis<<<(NN + 255) / 256, 256>>>();
    k_scan<<<1, 1024>>>();
    k_fill<<<(EE + 255) / 256, 256>>>(src, dst);

    k_gemm1<<<(NN + BM - 1) / BM, 256>>>(x, w1);
    k_gather1<<<(NN + 7) / 8, 256>>>(b1);
    k_gemm2<<<(NN + G2R - 1) / G2R, 256>>>(w2);
    k_gather2<<<(NN + 7) / 8, 256>>>(b2, out);

    k_hist1<<<(EE + 255) / 256, 256>>>(ew);
    k_sel1<<<1, 256>>>();
    k_hist2<<<(EE + 255) / 256, 256>>>(ew);
    k_sel2<<<1, 256>>>();

    k_loss<<<(EE + 255) / 256, 256>>>(src, dst, ew, lu);
    k_out_loss<<<1, 1>>>(out, out_size);
}

// round 7
// speedup vs baseline: 1.8330x; 1.0386x over previous
#include <cuda_runtime.h>
#include <cuda_bf16.h>
#include <math.h>

#define NN   100000
#define EE   3200000
#define FIN  512
#define HH   64
#define CC   40
#define KRANK 1600000u   // E - int(E*0.5): index into ascending sort

// ---------------- scratch (device globals; no allocation allowed) ----------
__device__ float          g_h[NN * HH];    // hs = (x @ w1) * dis[row]
__device__ float          g_h1[NN * HH];   // relu'd hidden layer
__device__ float          g_p[NN * CC];    // ps = (h1 @ w2) * dis[row]
__device__ float          g_x2[NN * CC];   // final logits (pre-log-softmax)
__device__ __nv_bfloat16  g_y[NN * CC];    // normalized logits (bf16, for loss dot)
__device__ float          g_dis[NN];       // (deg+1)^{-1/2}
__device__ int            g_deg[NN];
__device__ int            g_off[NN + 1];   // CSR row offsets (by dst)
__device__ int            g_cur[NN];       // fill cursors
__device__ int            g_csr[EE];       // src ids grouped by dst
__device__ unsigned       g_hist1[65536];
__device__ unsigned       g_hist2[65536];
__device__ unsigned       g_sel1[2];       // {hi bucket, residual rank}
__device__ float          g_thresh;
__device__ double         g_loss;

// ---------------- f32x2 packed helpers (FFMA2) ------------------------------
__device__ __forceinline__ unsigned long long pack2(float x, float y) {
    unsigned long long r;
    asm("mov.b64 %0, {%1, %2};" : "=l"(r) : "f"(x), "f"(y));
    return r;
}
__device__ __forceinline__ void unpack2(unsigned long long v, float& x, float& y) {
    asm("mov.b64 {%0, %1}, %2;" : "=f"(x), "=f"(y) : "l"(v));
}
__device__ __forceinline__ void ffma2(unsigned long long& d,
                                      unsigned long long a, unsigned long long b) {
    asm("fma.rn.f32x2 %0, %1, %2, %0;" : "+l"(d) : "l"(a), "l"(b));
}

// ---------------- degree + histogram (fused E-pass) -------------------------
__global__ void k_deg_hist(const int* __restrict__ dst, const float* __restrict__ ew) {
    int e = blockIdx.x * blockDim.x + threadIdx.x;
    if (e < EE) {
        atomicAdd(&g_deg[dst[e]], 1);
        unsigned u = __float_as_uint(ew[e]);   // positive floats: bit-monotone
        atomicAdd(&g_hist1[u >> 16], 1u);
    }
}

// ---------------- exclusive scan of deg -> off, cur, dis (single block) -----
__global__ __launch_bounds__(1024) void k_scan() {
    const int CH = (NN + 1023) / 1024;  // 98
    int t = threadIdx.x;
    int start = t * CH;
    int end = min(start + CH, NN);
    int s = 0;
    for (int i = start; i < end; i++) s += g_deg[i];

    __shared__ int wsum[32];
    int lane = t & 31, wid = t >> 5;
    int v = s;
#pragma unroll
    for (int o = 1; o < 32; o <<= 1) {
        int u = __shfl_up_sync(0xffffffffu, v, o);
        if (lane >= o) v += u;
    }
    if (lane == 31) wsum[wid] = v;
    __syncthreads();
    if (wid == 0) {
        int w = wsum[lane];
#pragma unroll
        for (int o = 1; o < 32; o <<= 1) {
            int u = __shfl_up_sync(0xffffffffu, w, o);
            if (lane >= o) w += u;
        }
        wsum[lane] = w;
    }
    __syncthreads();
    int base = v - s + (wid > 0 ? wsum[wid - 1] : 0);
    int run = base;
    for (int i = start; i < end; i++) {
        int d = g_deg[i];
        g_off[i] = run;
        g_cur[i] = run;
        g_dis[i] = rsqrtf((float)d + 1.0f);
        run += d;
    }
    if (start < NN && end == NN) g_off[NN] = run;
}

// ---------------- CSR fill ---------------------------------------------------
__global__ void k_fill(const int* __restrict__ src, const int* __restrict__ dst) {
    int e = blockIdx.x * blockDim.x + threadIdx.x;
    if (e < EE) {
        int pos = atomicAdd(&g_cur[dst[e]], 1);
        g_csr[pos] = src[e];
    }
}

// ---------------- GEMM1: hs = (x[N,512] @ w1[512,64]) * dis -----------------
// 128x64 tile, 8x4 micro-tile computed as 4 row-pairs via fma.rn.f32x2.
#define BM 128
#define BN 64
#define BK 16
__global__ __launch_bounds__(256) void k_gemm1(const float* __restrict__ x,
                                               const float* __restrict__ w1) {
    __shared__ float As[2][BK][BM];
    __shared__ float Bs[2][BK][BN];
    int tid = threadIdx.x;
    int row0 = blockIdx.x * BM;

    int ar = tid >> 1, ak = (tid & 1) * 8;          // A: 8 floats/thread
    int bk = tid >> 4, bc = (tid & 15) * 4;         // B: 4 floats/thread
    int ty = tid >> 4, tx = tid & 15;               // 8x4 micro-tile
    const bool rv = (row0 + ar) < NN;
    const float* xr = x + (size_t)(row0 + ar) * FIN + ak;

    unsigned long long acc[4][4];                    // [row-pair][col], two f32 each
#pragma unroll
    for (int i = 0; i < 4; i++)
#pragma unroll
        for (int j = 0; j < 4; j++) acc[i][j] = 0ull;

    float4 a0 = rv ? *(const float4*)(xr + 0) : make_float4(0, 0, 0, 0);
    float4 a1 = rv ? *(const float4*)(xr + 4) : make_float4(0, 0, 0, 0);
    float4 bb = *(const float4*)&w1[(size_t)bk * HH + bc];

    int buf = 0;
    for (int kt = 0; kt < FIN; kt += BK) {
        As[buf][ak + 0][ar] = a0.x; As[buf][ak + 1][ar] = a0.y;
        As[buf][ak + 2][ar] = a0.z; As[buf][ak + 3][ar] = a0.w;
        As[buf][ak + 4][ar] = a1.x; As[buf][ak + 5][ar] = a1.y;
        As[buf][ak + 6][ar] = a1.z; As[buf][ak + 7][ar] = a1.w;
        *(float4*)&Bs[buf][bk][bc] = bb;
        __syncthreads();

        if (kt + BK < FIN) {
            a0 = rv ? *(const float4*)(xr + kt + BK)     : make_float4(0, 0, 0, 0);
            a1 = rv ? *(const float4*)(xr + kt + BK + 4) : make_float4(0, 0, 0, 0);
            bb = *(const float4*)&w1[(size_t)(kt + BK + bk) * HH + bc];
        }
#pragma unroll
        for (int k = 0; k < BK; k++) {
            // row-pairs straight from shared (A rows are 32B-aligned)
            ulonglong2 A0 = *(const ulonglong2*)&As[buf][k][ty * 8];
            ulonglong2 A1 = *(const ulonglong2*)&As[buf][k][ty * 8 + 4];
            unsigned long long av[4] = {A0.x, A0.y, A1.x, A1.y};
            float4 B = *(float4*)&Bs[buf][k][tx * 4];
            unsigned long long bp[4] = {pack2(B.x, B.x), pack2(B.y, B.y),
                                        pack2(B.z, B.z), pack2(B.w, B.w)};
#pragma unroll
            for (int ip = 0; ip < 4; ip++)
#pragma unroll
                for (int j = 0; j < 4; j++) ffma2(acc[ip][j], av[ip], bp[j]);
        }
        buf ^= 1;
    }
#pragma unroll
    for (int ip = 0; ip < 4; ip++) {
        float lo[4], hi[4];
#pragma unroll
        for (int j = 0; j < 4; j++) unpack2(acc[ip][j], lo[j], hi[j]);
        int r = row0 + ty * 8 + 2 * ip;
        if (r < NN) {
            float dd = g_dis[r];
            *(float4*)&g_h[(size_t)r * HH + tx * 4] =
                make_float4(lo[0] * dd, lo[1] * dd, lo[2] * dd, lo[3] * dd);
        }
        if (r + 1 < NN) {
            float dd = g_dis[r + 1];
            *(float4*)&g_h[(size_t)(r + 1) * HH + tx * 4] =
                make_float4(hi[0] * dd, hi[1] * dd, hi[2] * dd, hi[3] * dd);
        }
    }
}

// ---------------- gather layer1 + relu/bias (warp per node) -----------------
__global__ __launch_bounds__(256) void k_gather1(const float* __restrict__ b1) {
    int n = blockIdx.x * 8 + (threadIdx.x >> 5);
    if (n >= NN) return;
    int lane = threadIdx.x & 31;
    const float2* hs2 = (const float2*)g_h;
    float2 acc = hs2[(size_t)n * 32 + lane];            // self-loop term (hs[n])
    int beg = g_off[n], end = g_off[n + 1];
#pragma unroll 4
    for (int i = beg; i < end; i++) {
        int s = __ldg(&g_csr[i]);                       // uniform across warp
        float2 v = __ldg(&hs2[(size_t)s * 32 + lane]);
        acc.x += v.x; acc.y += v.y;
    }
    float d = g_dis[n];
    float2 bv = ((const float2*)b1)[lane];
    float2 o;
    o.x = fmaxf(acc.x * d + bv.x, 0.f);
    o.y = fmaxf(acc.y * d + bv.y, 0.f);
    ((float2*)g_h1)[(size_t)n * 32 + lane] = o;
}

// ---------------- GEMM2: ps = (h1[N,64] @ w2[64,40]) * dis ------------------
#define G2R 64
__global__ __launch_bounds__(256) void k_gemm2(const float* __restrict__ w2) {
    __shared__ float Ah[G2R][HH + 4];   // stride 68 floats: 272B, 16B-aligned rows
    __shared__ float Ws[HH * CC];
    int tid = threadIdx.x;
    int row0 = blockIdx.x * G2R;
    for (int i = tid; i < HH * CC; i += 256) Ws[i] = w2[i];
    for (int i = tid; i < G2R * (HH / 4); i += 256) {
        int r = i >> 4, q = i & 15;
        float4 v = (row0 + r < NN) ? *(const float4*)&g_h1[(size_t)(row0 + r) * HH + q * 4]
                                   : make_float4(0.f, 0.f, 0.f, 0.f);
        *(float4*)&Ah[r][q * 4] = v;
    }
    __syncthreads();
    for (int o = tid; o < G2R * CC; o += 256) {
        int r = o / CC, c = o - r * CC;
        float s = 0.f;
#pragma unroll 16
        for (int k = 0; k < HH; k++) s += Ah[r][k] * Ws[k * CC + c];
        int row = row0 + r;
        if (row < NN) g_p[(size_t)row * CC + c] = s * g_dis[row];
    }
}

// ---- gather layer2 + bias + x2 + bf16 y + log_softmax (warp per node) ------
__global__ __launch_bounds__(256) void k_gather2(const float* __restrict__ b2,
                                                 float* __restrict__ out) {
    int n = blockIdx.x * 8 + (threadIdx.x >> 5);
    if (n >= NN) return;
    int lane = threadIdx.x & 31;
    bool hb = lane < (CC - 32);
    size_t base = (size_t)n * CC;
    float va = g_p[base + lane];                        // self-loop (ps[n])
    float vb = hb ? g_p[base + 32 + lane] : 0.f;
    int beg = g_off[n], end = g_off[n + 1];
#pragma unroll 4
    for (int i = beg; i < end; i++) {
        int s = __ldg(&g_csr[i]);
        size_t sb = (size_t)s * CC;
        va += __ldg(&g_p[sb + lane]);
        if (hb) vb += __ldg(&g_p[sb + 32 + lane]);
    }
    float d = g_dis[n];
    float xa = va * d + b2[lane];
    float xb = hb ? vb * d + b2[32 + lane] : 0.f;
    g_x2[base + lane] = xa;
    if (hb) g_x2[base + 32 + lane] = xb;

    // rnorm on all lanes (xor-reduce leaves full sum everywhere)
    float sq = xa * xa + (hb ? xb * xb : 0.f);
#pragma unroll
    for (int o = 16; o; o >>= 1) sq += __shfl_xor_sync(0xffffffffu, sq, o);
    float rn = 1.f / fmaxf(sqrtf(sq), 1e-8f);
    g_y[base + lane] = __float2bfloat16(xa * rn);
    if (hb) g_y[base + 32 + lane] = __float2bfloat16(xb * rn);

    float mx = fmaxf(xa, hb ? xb : -1e30f);
#pragma unroll
    for (int o = 16; o; o >>= 1) mx = fmaxf(mx, __shfl_xor_sync(0xffffffffu, mx, o));
    float se = expf(xa - mx) + (hb ? expf(xb - mx) : 0.f);
#pragma unroll
    for (int o = 16; o; o >>= 1) se += __shfl_xor_sync(0xffffffffu, se, o);
    float ls = logf(se);
    out[base + lane] = xa - mx - ls;
    if (hb) out[base + 32 + lane] = xb - mx - ls;
}

// ---------------- exact rank-select of edge_weight (2-pass radix) -----------
__global__ void k_sel1() {
    __shared__ unsigned part[256];
    __shared__ unsigned seg_s, rem_s;
    __shared__ unsigned s2[256];
    unsigned t = threadIdx.x;
    unsigned s = 0;
#pragma unroll 8
    for (int j = 0; j < 256; j++) s += g_hist1[t * 256 + j];
    part[t] = s;
    __syncthreads();
    if (t == 0) {
        unsigned k = KRANK, cum = 0;
        int sg = 0;
        for (; sg < 256; sg++) { if (cum + part[sg] > k) break; cum += part[sg]; }
        seg_s = sg; rem_s = k - cum;
    }
    __syncthreads();
    s2[t] = g_hist1[seg_s * 256 + t];
    __syncthreads();
    if (t == 0) {
        unsigned r = rem_s;
        int b = 0;
        for (; b < 256; b++) { if (r < s2[b]) break; r -= s2[b]; }
        g_sel1[0] = seg_s * 256 + b;
        g_sel1[1] = r;
    }
}

__global__ void k_hist2(const float* __restrict__ ew) {
    int e = blockIdx.x * blockDim.x + threadIdx.x;
    if (e < EE) {
        unsigned u = __float_as_uint(ew[e]);
        if ((u >> 16) == g_sel1[0]) atomicAdd(&g_hist2[u & 0xFFFFu], 1u);
    }
}

__global__ void k_sel2() {
    __shared__ unsigned part[256];
    __shared__ unsigned seg_s, rem_s;
    __shared__ unsigned s2[256];
    unsigned t = threadIdx.x;
    unsigned s = 0;
#pragma unroll 8
    for (int j = 0; j < 256; j++) s += g_hist2[t * 256 + j];
    part[t] = s;
    __syncthreads();
    if (t == 0) {
        unsigned k = g_sel1[1], cum = 0;
        int sg = 0;
        for (; sg < 256; sg++) { if (cum + part[sg] > k) break; cum += part[sg]; }
        seg_s = sg; rem_s = k - cum;
    }
    __syncthreads();
    s2[t] = g_hist2[seg_s * 256 + t];
    __syncthreads();
    if (t == 0) {
        unsigned r = rem_s;
        int b = 0;
        for (; b < 256; b++) { if (r < s2[b]) break; r -= s2[b]; }
        unsigned bits = (g_sel1[0] << 16) | (unsigned)(seg_s * 256 + b);
        g_thresh = __uint_as_float(bits);
    }
}

// ---------------- edge loss (bf16 normalized dot) ----------------------------
__device__ __forceinline__ float bf2dot(unsigned a, unsigned b) {
    float2 fa = __bfloat1622float2(*(const __nv_bfloat162*)&a);
    float2 fb = __bfloat1622float2(*(const __nv_bfloat162*)&b);
    return fa.x * fb.x + fa.y * fb.y;
}

__global__ __launch_bounds__(256) void k_loss(const int* __restrict__ src,
                                              const int* __restrict__ dst,
                                              const float* __restrict__ ew,
                                              const float* __restrict__ lu) {
    __shared__ float red_s[8];
    int e = blockIdx.x * blockDim.x + threadIdx.x;
    float contrib = 0.f;
    if (e < EE) {
        int s = src[e], d = dst[e];
        // 80 B per node, 16B-aligned (80 = 5*16)
        const uint4* A = (const uint4*)&g_y[(size_t)s * CC];
        const uint4* B = (const uint4*)&g_y[(size_t)d * CC];
        float dot = 0.f;
#pragma unroll
        for (int q = 0; q < 5; q++) {
            uint4 ua = A[q], ub = B[q];
            dot += bf2dot(ua.x, ub.x) + bf2dot(ua.y, ub.y)
                 + bf2dot(ua.z, ub.z) + bf2dot(ua.w, ub.w);
        }
        float w = ew[e];
        bool m = (w >= g_thresh);
        float cs = 1.f - dot;           // cosine_sim
        float lp = m ? cs : (1.f - cs); // where(mask, 1-cos, cos)
        float le = m ? w : (1.f - w);
        contrib = le * lp * lu[e];
    }
#pragma unroll
    for (int o = 16; o; o >>= 1) contrib += __shfl_xor_sync(0xffffffffu, contrib, o);
    int lane = threadIdx.x & 31, wid = threadIdx.x >> 5;
    if (lane == 0) red_s[wid] = contrib;
    __syncthreads();
    if (wid == 0) {
        float v = (lane < 8) ? red_s[lane] : 0.f;
#pragma unroll
        for (int o = 4; o; o >>= 1) v += __shfl_xor_sync(0xffffffffu, v, o);
        if (lane == 0) atomicAdd(&g_loss, (double)v);
    }
}

__global__ void k_out_loss(float* out, int out_size) {
    if (out_size > NN * CC) out[out_size - 1] = (float)(g_loss / (double)EE);
}

// ---------------- launch ----------------------------------------------------
extern "C" void kernel_launch(void* const* d_in, const int* in_sizes, int n_in,
                              void* d_out, int out_size) {
    const float* x  = (const float*)d_in[0];
    const int*   ei = (const int*)d_in[1];
    const float* ew = (const float*)d_in[2];
    const float* lu = (const float*)d_in[3];
    const float* w1 = (const float*)d_in[4];
    const float* b1 = (const float*)d_in[5];
    const float* w2 = (const float*)d_in[6];
    const float* b2 = (const float*)d_in[7];
    float* out = (float*)d_out;

    const int* src = ei;
    const int* dst = ei + EE;

    void *p_deg, *p_h1, *p_h2, *p_loss;
    cudaGetSymbolAddress(&p_deg,  g_deg);
    cudaGetSymbolAddress(&p_h1,   g_hist1);
    cudaGetSymbolAddress(&p_h2,   g_hist2);
    cudaGetSymbolAddress(&p_loss, g_loss);

    cudaMemsetAsync(p_deg,  0, sizeof(g_deg));
    cudaMemsetAsync(p_h1,   0, sizeof(g_hist1));
    cudaMemsetAsync(p_h2,   0, sizeof(g_hist2));
    cudaMemsetAsync(p_loss, 0, sizeof(g_loss));

    k_deg_hist<<<(EE + 255) / 256, 256>>>(dst, ew);
    k_scan<<<1, 1024>>>();
    k_fill<<<(EE + 255) / 256, 256>>>(src, dst);
    k_sel1<<<1, 256>>>();
    k_hist2<<<(EE + 255) / 256, 256>>>(ew);
    k_sel2<<<1, 256>>>();

    k_gemm1<<<(NN + BM - 1) / BM, 256>>>(x, w1);
    k_gather1<<<(NN + 7) / 8, 256>>>(b1);
    k_gemm2<<<(NN + G2R - 1) / G2R, 256>>>(w2);
    k_gather2<<<(NN + 7) / 8, 256>>>(b2, out);

    k_loss<<<(EE + 255) / 256, 256>>>(src, dst, ew, lu);
    k_out_loss<<<1, 1>>>(out, out_size);
}

// round 8
// speedup vs baseline: 1.8792x; 1.0252x over previous
#include <cuda_runtime.h>
#include <cuda_bf16.h>
#include <math.h>

#define NN   100000
#define EE   3200000
#define FIN  512
#define HH   64
#define CC   40
#define KRANK 1600000u   // E - int(E*0.5): index into ascending sort

// ---------------- zeroed blob (single memset) -------------------------------
#define OFF_DEG    0
#define OFF_H1     (OFF_DEG + NN)           // fine hist1 (65536)
#define OFF_H1C    (OFF_H1 + 65536)         // coarse hist1 (256)
#define OFF_H2     (OFF_H1C + 256)          // fine hist2 (65536)
#define OFF_H2C    (OFF_H2 + 65536)         // coarse hist2 (256)
#define OFF_DONE   (OFF_H2C + 256)          // done counter (even offset)
#define OFF_LOSS   (OFF_DONE + 2)           // double accumulator (8B aligned)
#define ZWORDS     (OFF_LOSS + 2)
__device__ __align__(8) unsigned g_zero[ZWORDS];

// ---------------- other scratch ---------------------------------------------
__device__ float          g_h[NN * HH];    // hs = (x @ w1) * dis[row]
__device__ float          g_h1[NN * HH];   // relu'd hidden
__device__ float          g_p[NN * CC];    // ps = (h1 @ w2) * dis[row]
__device__ float          g_x2[NN * CC];   // final logits
__device__ __nv_bfloat16  g_y[NN * CC];    // normalized logits (bf16)
__device__ float          g_dis[NN];       // (deg+1)^{-1/2}
__device__ int            g_off[NN + 1];
__device__ int            g_cur[NN];
__device__ int            g_csr[EE];
__device__ unsigned       g_sel[2];        // {fine bucket (u>>16), residual rank}
__device__ float          g_thresh;

// ---------------- f32x2 packed helpers (FFMA2) ------------------------------
__device__ __forceinline__ unsigned long long pack2(float x, float y) {
    unsigned long long r;
    asm("mov.b64 %0, {%1, %2};" : "=l"(r) : "f"(x), "f"(y));
    return r;
}
__device__ __forceinline__ void unpack2(unsigned long long v, float& x, float& y) {
    asm("mov.b64 {%0, %1}, %2;" : "=f"(x), "=f"(y) : "l"(v));
}
__device__ __forceinline__ void ffma2(unsigned long long& d,
                                      unsigned long long a, unsigned long long b) {
    asm("fma.rn.f32x2 %0, %1, %2, %0;" : "+l"(d) : "l"(a), "l"(b));
}

// ---------------- degree + fine/coarse hist1 (one E-pass, 4 edges/thread) ---
__global__ __launch_bounds__(256) void k_deg_hist(const int* __restrict__ dst,
                                                  const float* __restrict__ ew) {
    __shared__ unsigned ch[256];
    int tid = threadIdx.x;
    ch[tid] = 0;
    __syncthreads();
    int e = (blockIdx.x * 256 + tid) * 4;          // EE = 3125*1024 exactly
    int4   d4 = *(const int4*)&dst[e];
    float4 w4 = *(const float4*)&ew[e];
    int* deg = (int*)&g_zero[OFF_DEG];
    unsigned* h1 = &g_zero[OFF_H1];
    atomicAdd(&deg[d4.x], 1); atomicAdd(&deg[d4.y], 1);
    atomicAdd(&deg[d4.z], 1); atomicAdd(&deg[d4.w], 1);
    unsigned u;
    u = __float_as_uint(w4.x); atomicAdd(&h1[u >> 16], 1u); atomicAdd(&ch[u >> 24], 1u);
    u = __float_as_uint(w4.y); atomicAdd(&h1[u >> 16], 1u); atomicAdd(&ch[u >> 24], 1u);
    u = __float_as_uint(w4.z); atomicAdd(&h1[u >> 16], 1u); atomicAdd(&ch[u >> 24], 1u);
    u = __float_as_uint(w4.w); atomicAdd(&h1[u >> 16], 1u); atomicAdd(&ch[u >> 24], 1u);
    __syncthreads();
    if (ch[tid]) atomicAdd(&g_zero[OFF_H1C + tid], ch[tid]);
}

// ---------------- scan (block 0) + sel1 (block 1) ---------------------------
__global__ __launch_bounds__(1024) void k_scan_sel1() {
    if (blockIdx.x == 0) {
        const int CH2 = 100;                       // 1000 active threads
        int t = threadIdx.x;
        int start = t * CH2;
        const int* deg = (const int*)&g_zero[OFF_DEG];
        int s = 0;
        if (start < NN) {
#pragma unroll
            for (int q = 0; q < 25; q++) {
                int4 dv = *(const int4*)&deg[start + q * 4];
                s += dv.x + dv.y + dv.z + dv.w;
            }
        }
        __shared__ int wsum[32];
        int lane = t & 31, wid = t >> 5;
        int v = s;
#pragma unroll
        for (int o = 1; o < 32; o <<= 1) {
            int u = __shfl_up_sync(0xffffffffu, v, o);
            if (lane >= o) v += u;
        }
        if (lane == 31) wsum[wid] = v;
        __syncthreads();
        if (wid == 0) {
            int w = wsum[lane];
#pragma unroll
            for (int o = 1; o < 32; o <<= 1) {
                int u = __shfl_up_sync(0xffffffffu, w, o);
                if (lane >= o) w += u;
            }
            wsum[lane] = w;
        }
        __syncthreads();
        int base = v - s + (wid > 0 ? wsum[wid - 1] : 0);
        if (start < NN) {
            int run = base;
#pragma unroll
            for (int q = 0; q < 25; q++) {
                int idx = start + q * 4;
                int4 dv = *(const int4*)&deg[idx];
                int4 off; float4 ds;
                off.x = run; ds.x = rsqrtf((float)dv.x + 1.f); run += dv.x;
                off.y = run; ds.y = rsqrtf((float)dv.y + 1.f); run += dv.y;
                off.z = run; ds.z = rsqrtf((float)dv.z + 1.f); run += dv.z;
                off.w = run; ds.w = rsqrtf((float)dv.w + 1.f); run += dv.w;
                *(int4*)&g_off[idx]  = off;
                *(int4*)&g_cur[idx]  = off;
                *(float4*)&g_dis[idx] = ds;
            }
            if (start + CH2 >= NN) g_off[NN] = run;
        }
    } else {
        __shared__ unsigned c[256];
        __shared__ unsigned scg, srem;
        int t = threadIdx.x;
        if (t < 256) c[t] = g_zero[OFF_H1C + t];
        __syncthreads();
        if (t == 0) {
            unsigned k = KRANK, cum = 0; int cg = 0;
            for (; cg < 256; cg++) { if (cum + c[cg] > k) break; cum += c[cg]; }
            scg = cg; srem = k - cum;
        }
        __syncthreads();
        if (t < 256) c[t] = g_zero[OFF_H1 + scg * 256 + t];
        __syncthreads();
        if (t == 0) {
            unsigned r = srem; int b = 0;
            for (; b < 256; b++) { if (r < c[b]) break; r -= c[b]; }
            g_sel[0] = scg * 256 + b;
            g_sel[1] = r;
        }
    }
}

// ---------------- fat1: gemm1 (bid%5==0) interleaved with fill+hist2 --------
#define BM 128
#define BK 16
#define G1B 782                               // ceil(NN/128)
#define EB1 3125                              // edge blocks (1024 edges each)

__device__ __forceinline__ void gemm1_body(const float* __restrict__ x,
                                           const float* __restrict__ w1, int blk) {
    __shared__ float As[2][BK][BM];
    __shared__ float Bs[2][BK][HH];
    int tid = threadIdx.x;
    int row0 = blk * BM;

    int ar = tid >> 1, ak = (tid & 1) * 8;
    int bk = tid >> 4, bc = (tid & 15) * 4;
    int ty = tid >> 4, tx = tid & 15;
    const bool rv = (row0 + ar) < NN;
    const float* xr = x + (size_t)(row0 + ar) * FIN + ak;

    unsigned long long acc[4][4];
#pragma unroll
    for (int i = 0; i < 4; i++)
#pragma unroll
        for (int j = 0; j < 4; j++) acc[i][j] = 0ull;

    float4 a0 = rv ? *(const float4*)(xr + 0) : make_float4(0, 0, 0, 0);
    float4 a1 = rv ? *(const float4*)(xr + 4) : make_float4(0, 0, 0, 0);
    float4 bb = *(const float4*)&w1[(size_t)bk * HH + bc];

    int buf = 0;
    for (int kt = 0; kt < FIN; kt += BK) {
        As[buf][ak + 0][ar] = a0.x; As[buf][ak + 1][ar] = a0.y;
        As[buf][ak + 2][ar] = a0.z; As[buf][ak + 3][ar] = a0.w;
        As[buf][ak + 4][ar] = a1.x; As[buf][ak + 5][ar] = a1.y;
        As[buf][ak + 6][ar] = a1.z; As[buf][ak + 7][ar] = a1.w;
        *(float4*)&Bs[buf][bk][bc] = bb;
        __syncthreads();
        if (kt + BK < FIN) {
            a0 = rv ? *(const float4*)(xr + kt + BK)     : make_float4(0, 0, 0, 0);
            a1 = rv ? *(const float4*)(xr + kt + BK + 4) : make_float4(0, 0, 0, 0);
            bb = *(const float4*)&w1[(size_t)(kt + BK + bk) * HH + bc];
        }
#pragma unroll
        for (int k = 0; k < BK; k++) {
            ulonglong2 A0 = *(const ulonglong2*)&As[buf][k][ty * 8];
            ulonglong2 A1 = *(const ulonglong2*)&As[buf][k][ty * 8 + 4];
            unsigned long long av[4] = {A0.x, A0.y, A1.x, A1.y};
            float4 B = *(float4*)&Bs[buf][k][tx * 4];
            unsigned long long bp[4] = {pack2(B.x, B.x), pack2(B.y, B.y),
                                        pack2(B.z, B.z), pack2(B.w, B.w)};
#pragma unroll
            for (int ip = 0; ip < 4; ip++)
#pragma unroll
                for (int j = 0; j < 4; j++) ffma2(acc[ip][j], av[ip], bp[j]);
        }
        buf ^= 1;
    }
#pragma unroll
    for (int ip = 0; ip < 4; ip++) {
        float lo[4], hi[4];
#pragma unroll
        for (int j = 0; j < 4; j++) unpack2(acc[ip][j], lo[j], hi[j]);
        int r = row0 + ty * 8 + 2 * ip;
        if (r < NN) {
            float dd = g_dis[r];
            *(float4*)&g_h[(size_t)r * HH + tx * 4] =
                make_float4(lo[0] * dd, lo[1] * dd, lo[2] * dd, lo[3] * dd);
        }
        if (r + 1 < NN) {
            float dd = g_dis[r + 1];
            *(float4*)&g_h[(size_t)(r + 1) * HH + tx * 4] =
                make_float4(hi[0] * dd, hi[1] * dd, hi[2] * dd, hi[3] * dd);
        }
    }
}

__global__ __launch_bounds__(256) void k_fat1(const float* __restrict__ x,
                                              const float* __restrict__ w1,
                                              const int* __restrict__ src,
                                              const int* __restrict__ dst,
                                              const float* __restrict__ ew) {
    int bid = blockIdx.x;
    int g = bid / 5, r = bid - g * 5;
    if (r == 0) {
        gemm1_body(x, w1, g);
    } else {
        int eb = g * 4 + (r - 1);
        if (eb >= EB1) return;
        int e = eb * 1024 + threadIdx.x * 4;
        int4   s4 = *(const int4*)&src[e];
        int4   d4 = *(const int4*)&dst[e];
        float4 w4 = *(const float4*)&ew[e];
        int p0 = atomicAdd(&g_cur[d4.x], 1); g_csr[p0] = s4.x;
        int p1 = atomicAdd(&g_cur[d4.y], 1); g_csr[p1] = s4.y;
        int p2 = atomicAdd(&g_cur[d4.z], 1); g_csr[p2] = s4.z;
        int p3 = atomicAdd(&g_cur[d4.w], 1); g_csr[p3] = s4.w;
        unsigned selb = g_sel[0];
        unsigned u;
        u = __float_as_uint(w4.x);
        if ((u >> 16) == selb) { atomicAdd(&g_zero[OFF_H2 + (u & 0xFFFFu)], 1u);
                                 atomicAdd(&g_zero[OFF_H2C + ((u >> 8) & 0xFFu)], 1u); }
        u = __float_as_uint(w4.y);
        if ((u >> 16) == selb) { atomicAdd(&g_zero[OFF_H2 + (u & 0xFFFFu)], 1u);
                                 atomicAdd(&g_zero[OFF_H2C + ((u >> 8) & 0xFFu)], 1u); }
        u = __float_as_uint(w4.z);
        if ((u >> 16) == selb) { atomicAdd(&g_zero[OFF_H2 + (u & 0xFFFFu)], 1u);
                                 atomicAdd(&g_zero[OFF_H2C + ((u >> 8) & 0xFFu)], 1u); }
        u = __float_as_uint(w4.w);
        if ((u >> 16) == selb) { atomicAdd(&g_zero[OFF_H2 + (u & 0xFFFFu)], 1u);
                                 atomicAdd(&g_zero[OFF_H2C + ((u >> 8) & 0xFFu)], 1u); }
    }
}

// ---------------- fat2: sel2 (block 0) + gather1 (blocks 1..) ---------------
__global__ __launch_bounds__(256) void k_fat2(const float* __restrict__ b1) {
    if (blockIdx.x == 0) {
        __shared__ unsigned c[256];
        __shared__ unsigned scg, srem;
        int t = threadIdx.x;
        c[t] = g_zero[OFF_H2C + t];
        __syncthreads();
        if (t == 0) {
            unsigned k = g_sel[1], cum = 0; int cg = 0;
            for (; cg < 256; cg++) { if (cum + c[cg] > k) break; cum += c[cg]; }
            scg = cg; srem = k - cum;
        }
        __syncthreads();
        c[t] = g_zero[OFF_H2 + scg * 256 + t];
        __syncthreads();
        if (t == 0) {
            unsigned r = srem; int b = 0;
            for (; b < 256; b++) { if (r < c[b]) break; r -= c[b]; }
            unsigned bits = (g_sel[0] << 16) | (unsigned)(scg * 256 + b);
            g_thresh = __uint_as_float(bits);
        }
        return;
    }
    int n = (blockIdx.x - 1) * 8 + (threadIdx.x >> 5);
    if (n >= NN) return;
    int lane = threadIdx.x & 31;
    const float2* hs2 = (const float2*)g_h;
    float2 acc = hs2[(size_t)n * 32 + lane];            // self-loop (hs[n])
    int beg = g_off[n], end = g_off[n + 1];
    int i = beg;
    for (; i + 8 <= end; i += 8) {
        int sid[8];
#pragma unroll
        for (int j = 0; j < 8; j++) sid[j] = __ldg(&g_csr[i + j]);
        float2 v[8];
#pragma unroll
        for (int j = 0; j < 8; j++) v[j] = __ldg(&hs2[(size_t)sid[j] * 32 + lane]);
#pragma unroll
        for (int j = 0; j < 8; j++) { acc.x += v[j].x; acc.y += v[j].y; }
    }
    for (; i < end; i++) {
        int s = __ldg(&g_csr[i]);
        float2 v = __ldg(&hs2[(size_t)s * 32 + lane]);
        acc.x += v.x; acc.y += v.y;
    }
    float d = g_dis[n];
    float2 bv = ((const float2*)b1)[lane];
    float2 o;
    o.x = fmaxf(acc.x * d + bv.x, 0.f);
    o.y = fmaxf(acc.y * d + bv.y, 0.f);
    ((float2*)g_h1)[(size_t)n * 32 + lane] = o;
}

// ---------------- GEMM2: ps = (h1[N,64] @ w2[64,40]) * dis ------------------
#define G2R 64
__global__ __launch_bounds__(256) void k_gemm2(const float* __restrict__ w2) {
    __shared__ float Ah[G2R][HH + 4];
    __shared__ float Ws[HH * CC];
    int tid = threadIdx.x;
    int row0 = blockIdx.x * G2R;
    for (int i = tid; i < HH * CC; i += 256) Ws[i] = w2[i];
    for (int i = tid; i < G2R * (HH / 4); i += 256) {
        int r = i >> 4, q = i & 15;
        float4 v = (row0 + r < NN) ? *(const float4*)&g_h1[(size_t)(row0 + r) * HH + q * 4]
                                   : make_float4(0.f, 0.f, 0.f, 0.f);
        *(float4*)&Ah[r][q * 4] = v;
    }
    __syncthreads();
    for (int o = tid; o < G2R * CC; o += 256) {
        int r = o / CC, c = o - r * CC;
        float s = 0.f;
#pragma unroll 16
        for (int k = 0; k < HH; k++) s += Ah[r][k] * Ws[k * CC + c];
        int row = row0 + r;
        if (row < NN) g_p[(size_t)row * CC + c] = s * g_dis[row];
    }
}

// ---- gather2 + bias + x2 + bf16 y + log_softmax (warp per node) ------------
__global__ __launch_bounds__(256) void k_gather2(const float* __restrict__ b2,
                                                 float* __restrict__ out) {
    int n = blockIdx.x * 8 + (threadIdx.x >> 5);
    if (n >= NN) return;
    int lane = threadIdx.x & 31;
    bool hb = lane < (CC - 32);
    size_t base = (size_t)n * CC;
    float va = g_p[base + lane];
    float vb = hb ? g_p[base + 32 + lane] : 0.f;
    int beg = g_off[n], end = g_off[n + 1];
    int i = beg;
    for (; i + 4 <= end; i += 4) {
        int sid[4];
#pragma unroll
        for (int j = 0; j < 4; j++) sid[j] = __ldg(&g_csr[i + j]);
        float a[4], b[4];
#pragma unroll
        for (int j = 0; j < 4; j++) {
            size_t sb = (size_t)sid[j] * CC;
            a[j] = __ldg(&g_p[sb + lane]);
            b[j] = hb ? __ldg(&g_p[sb + 32 + lane]) : 0.f;
        }
#pragma unroll
        for (int j = 0; j < 4; j++) { va += a[j]; vb += b[j]; }
    }
    for (; i < end; i++) {
        int s = __ldg(&g_csr[i]);
        size_t sb = (size_t)s * CC;
        va += __ldg(&g_p[sb + lane]);
        if (hb) vb += __ldg(&g_p[sb + 32 + lane]);
    }
    float d = g_dis[n];
    float xa = va * d + b2[lane];
    float xb = hb ? vb * d + b2[32 + lane] : 0.f;
    g_x2[base + lane] = xa;
    if (hb) g_x2[base + 32 + lane] = xb;

    float sq = xa * xa + (hb ? xb * xb : 0.f);
#pragma unroll
    for (int o = 16; o; o >>= 1) sq += __shfl_xor_sync(0xffffffffu, sq, o);
    float rn = 1.f / fmaxf(sqrtf(sq), 1e-8f);
    g_y[base + lane] = __float2bfloat16(xa * rn);
    if (hb) g_y[base + 32 + lane] = __float2bfloat16(xb * rn);

    float mx = fmaxf(xa, hb ? xb : -1e30f);
#pragma unroll
    for (int o = 16; o; o >>= 1) mx = fmaxf(mx, __shfl_xor_sync(0xffffffffu, mx, o));
    float se = expf(xa - mx) + (hb ? expf(xb - mx) : 0.f);
#pragma unroll
    for (int o = 16; o; o >>= 1) se += __shfl_xor_sync(0xffffffffu, se, o);
    float ls = logf(se);
    out[base + lane] = xa - mx - ls;
    if (hb) out[base + 32 + lane] = xb - mx - ls;
}

// ---------------- edge loss (bf16 normalized dot) + fused final write -------
__device__ __forceinline__ float bf2dot(unsigned a, unsigned b) {
    float2 fa = __bfloat1622float2(*(const __nv_bfloat162*)&a);
    float2 fb = __bfloat1622float2(*(const __nv_bfloat162*)&b);
    return fa.x * fb.x + fa.y * fb.y;
}

__global__ __launch_bounds__(256) void k_loss(const int* __restrict__ src,
                                              const int* __restrict__ dst,
                                              const float* __restrict__ ew,
                                              const float* __restrict__ lu,
                                              float* __restrict__ out,
                                              int out_size) {
    __shared__ float red_s[8];
    int e = blockIdx.x * blockDim.x + threadIdx.x;
    float contrib = 0.f;
    if (e < EE) {
        int s = src[e], d = dst[e];
        const uint4* A = (const uint4*)&g_y[(size_t)s * CC];
        const uint4* B = (const uint4*)&g_y[(size_t)d * CC];
        float dot = 0.f;
#pragma unroll
        for (int q = 0; q < 5; q++) {
            uint4 ua = A[q], ub = B[q];
            dot += bf2dot(ua.x, ub.x) + bf2dot(ua.y, ub.y)
                 + bf2dot(ua.z, ub.z) + bf2dot(ua.w, ub.w);
        }
        float w = ew[e];
        bool m = (w >= g_thresh);
        float cs = 1.f - dot;
        float lp = m ? cs : (1.f - cs);
        float le = m ? w : (1.f - w);
        contrib = le * lp * lu[e];
    }
#pragma unroll
    for (int o = 16; o; o >>= 1) contrib += __shfl_xor_sync(0xffffffffu, contrib, o);
    int lane = threadIdx.x & 31, wid = threadIdx.x >> 5;
    if (lane == 0) red_s[wid] = contrib;
    __syncthreads();
    if (wid == 0 && lane == 0) {
        float v = 0.f;
#pragma unroll
        for (int j = 0; j < 8; j++) v += red_s[j];
        atomicAdd((double*)&g_zero[OFF_LOSS], (double)v);
        __threadfence();
        unsigned old = atomicAdd(&g_zero[OFF_DONE], 1u);
        if (old == gridDim.x - 1) {
            __threadfence();
            double L = *(volatile double*)&g_zero[OFF_LOSS];
            if (out_size > NN * CC) out[out_size - 1] = (float)(L / (double)EE);
        }
    }
}

// ---------------- launch ----------------------------------------------------
extern "C" void kernel_launch(void* const* d_in, const int* in_sizes, int n_in,
                              void* d_out, int out_size) {
    const float* x  = (const float*)d_in[0];
    const int*   ei = (const int*)d_in[1];
    const float* ew = (const float*)d_in[2];
    const float* lu = (const float*)d_in[3];
    const float* w1 = (const float*)d_in[4];
    const float* b1 = (const float*)d_in[5];
    const float* w2 = (const float*)d_in[6];
    const float* b2 = (const float*)d_in[7];
    float* out = (float*)d_out;

    const int* src = ei;
    const int* dst = ei + EE;

    void* p_zero;
    cudaGetSymbolAddress(&p_zero, g_zero);
    cudaMemsetAsync(p_zero, 0, sizeof(g_zero));

    k_deg_hist<<<EE / 1024, 256>>>(dst, ew);
    k_scan_sel1<<<2, 1024>>>();
    k_fat1<<<G1B * 5, 256>>>(x, w1, src, dst, ew);
    k_fat2<<<(NN + 7) / 8 + 1, 256>>>(b1);
    k_gemm2<<<(NN + G2R - 1) / G2R, 256>>>(w2);
    k_gather2<<<(NN + 7) / 8, 256>>>(b2, out);
    k_loss<<<EE / 256, 256>>>(src, dst, ew, lu, out, out_size);
}

// round 10
// speedup vs baseline: 1.9220x; 1.0228x over previous
#include <cuda_runtime.h>
#include <cuda_bf16.h>
#include <math.h>

#define NN   100000
#define EE   3200000
#define FIN  512
#define HH   64
#define CC   40
#define KRANK 1600000u   // E - int(E*0.5): index into ascending sort

// ---------------- zeroed blob (single memset) -------------------------------
#define OFF_DEG    0
#define OFF_H1     (OFF_DEG + NN)           // fine hist1 (65536)
#define OFF_H1C    (OFF_H1 + 65536)         // coarse hist1 (256)
#define OFF_H2     (OFF_H1C + 256)          // fine hist2 (65536)
#define OFF_H2C    (OFF_H2 + 65536)         // coarse hist2 (256)
#define OFF_DONE   (OFF_H2C + 256)          // done counter
#define OFF_LOSS   (OFF_DONE + 2)           // double accumulator (8B aligned)
#define ZWORDS     (OFF_LOSS + 2)
__device__ __align__(8) unsigned g_zero[ZWORDS];

// ---------------- other scratch ---------------------------------------------
__device__ float          g_h[NN * HH];    // hs = (x @ w1) * dis[row]
__device__ float          g_p[NN * CC];    // ps = (h1 @ w2) * dis[row]
__device__ __nv_bfloat16  g_y[NN * CC];    // normalized logits (bf16)
__device__ float          g_dis[NN];       // (deg+1)^{-1/2}
__device__ int            g_off[NN + 1];
__device__ int            g_cur[NN];
__device__ int            g_csr[EE];       // src grouped by dst
__device__ int            g_dstp[EE];      // dst id per CSR position
__device__ float          g_ewp[EE];       // edge weight per CSR position
__device__ float          g_lup[EE];       // l_u per CSR position
__device__ unsigned       g_sel[2];        // {fine bucket (u>>16), residual rank}
__device__ float          g_thresh;

// ---------------- f32x2 packed helpers (FFMA2) ------------------------------
__device__ __forceinline__ unsigned long long pack2(float x, float y) {
    unsigned long long r;
    asm("mov.b64 %0, {%1, %2};" : "=l"(r) : "f"(x), "f"(y));
    return r;
}
__device__ __forceinline__ void unpack2(unsigned long long v, float& x, float& y) {
    asm("mov.b64 {%0, %1}, %2;" : "=f"(x), "=f"(y) : "l"(v));
}
__device__ __forceinline__ void ffma2(unsigned long long& d,
                                      unsigned long long a, unsigned long long b) {
    asm("fma.rn.f32x2 %0, %1, %2, %0;" : "+l"(d) : "l"(a), "l"(b));
}

// ---------------- degree + fine/coarse hist1 (one E-pass, 4 edges/thread) ---
__global__ __launch_bounds__(256) void k_deg_hist(const int* __restrict__ dst,
                                                  const float* __restrict__ ew) {
    __shared__ unsigned ch[256];
    int tid = threadIdx.x;
    ch[tid] = 0;
    __syncthreads();
    int e = (blockIdx.x * 256 + tid) * 4;          // EE = 3125*1024 exactly
    int4   d4 = *(const int4*)&dst[e];
    float4 w4 = *(const float4*)&ew[e];
    int* deg = (int*)&g_zero[OFF_DEG];
    unsigned* h1 = &g_zero[OFF_H1];
    atomicAdd(&deg[d4.x], 1); atomicAdd(&deg[d4.y], 1);
    atomicAdd(&deg[d4.z], 1); atomicAdd(&deg[d4.w], 1);
    unsigned u;
    u = __float_as_uint(w4.x); atomicAdd(&h1[u >> 16], 1u); atomicAdd(&ch[u >> 24], 1u);
    u = __float_as_uint(w4.y); atomicAdd(&h1[u >> 16], 1u); atomicAdd(&ch[u >> 24], 1u);
    u = __float_as_uint(w4.z); atomicAdd(&h1[u >> 16], 1u); atomicAdd(&ch[u >> 24], 1u);
    u = __float_as_uint(w4.w); atomicAdd(&h1[u >> 16], 1u); atomicAdd(&ch[u >> 24], 1u);
    __syncthreads();
    if (ch[tid]) atomicAdd(&g_zero[OFF_H1C + tid], ch[tid]);
}

// ---------------- scan (block 0) + sel1 (block 1) ---------------------------
__global__ __launch_bounds__(1024) void k_scan_sel1() {
    if (blockIdx.x == 0) {
        const int CH2 = 100;                       // 1000 active threads
        int t = threadIdx.x;
        int start = t * CH2;
        const int* deg = (const int*)&g_zero[OFF_DEG];
        int s = 0;
        if (start < NN) {
#pragma unroll
            for (int q = 0; q < 25; q++) {
                int4 dv = *(const int4*)&deg[start + q * 4];
                s += dv.x + dv.y + dv.z + dv.w;
            }
        }
        __shared__ int wsum[32];
        int lane = t & 31, wid = t >> 5;
        int v = s;
#pragma unroll
        for (int o = 1; o < 32; o <<= 1) {
            int u = __shfl_up_sync(0xffffffffu, v, o);
            if (lane >= o) v += u;
        }
        if (lane == 31) wsum[wid] = v;
        __syncthreads();
        if (wid == 0) {
            int w = wsum[lane];
#pragma unroll
            for (int o = 1; o < 32; o <<= 1) {
                int u = __shfl_up_sync(0xffffffffu, w, o);
                if (lane >= o) w += u;
            }
            wsum[lane] = w;
        }
        __syncthreads();
        int base = v - s + (wid > 0 ? wsum[wid - 1] : 0);
        if (start < NN) {
            int run = base;
#pragma unroll
            for (int q = 0; q < 25; q++) {
                int idx = start + q * 4;
                int4 dv = *(const int4*)&deg[idx];
                int4 off; float4 ds;
                off.x = run; ds.x = rsqrtf((float)dv.x + 1.f); run += dv.x;
                off.y = run; ds.y = rsqrtf((float)dv.y + 1.f); run += dv.y;
                off.z = run; ds.z = rsqrtf((float)dv.z + 1.f); run += dv.z;
                off.w = run; ds.w = rsqrtf((float)dv.w + 1.f); run += dv.w;
                *(int4*)&g_off[idx]  = off;
                *(int4*)&g_cur[idx]  = off;
                *(float4*)&g_dis[idx] = ds;
            }
            if (start + CH2 >= NN) g_off[NN] = run;
        }
    } else {
        __shared__ unsigned c[256];
        __shared__ unsigned scg, srem;
        int t = threadIdx.x;
        if (t < 256) c[t] = g_zero[OFF_H1C + t];
        __syncthreads();
        if (t == 0) {
            unsigned k = KRANK, cum = 0; int cg = 0;
            for (; cg < 256; cg++) { if (cum + c[cg] > k) break; cum += c[cg]; }
            scg = cg; srem = k - cum;
        }
        __syncthreads();
        if (t < 256) c[t] = g_zero[OFF_H1 + scg * 256 + t];
        __syncthreads();
        if (t == 0) {
            unsigned r = srem; int b = 0;
            for (; b < 256; b++) { if (r < c[b]) break; r -= c[b]; }
            g_sel[0] = scg * 256 + b;
            g_sel[1] = r;
        }
    }
}

// ---------------- fat1: gemm1 (bid%5==0) interleaved with fill+hist2 --------
#define BM 128
#define BK 16
#define G1B 782                               // ceil(NN/128)
#define EB1 3125                              // edge blocks (1024 edges each)

__device__ __forceinline__ void gemm1_body(const float* __restrict__ x,
                                           const float* __restrict__ w1, int blk) {
    __shared__ float As[2][BK][BM];
    __shared__ float Bs[2][BK][HH];
    int tid = threadIdx.x;
    int row0 = blk * BM;

    int ar = tid >> 1, ak = (tid & 1) * 8;
    int bk = tid >> 4, bc = (tid & 15) * 4;
    int ty = tid >> 4, tx = tid & 15;
    const bool rv = (row0 + ar) < NN;
    const float* xr = x + (size_t)(row0 + ar) * FIN + ak;

    unsigned long long acc[4][4];
#pragma unroll
    for (int i = 0; i < 4; i++)
#pragma unroll
        for (int j = 0; j < 4; j++) acc[i][j] = 0ull;

    float4 a0 = rv ? *(const float4*)(xr + 0) : make_float4(0, 0, 0, 0);
    float4 a1 = rv ? *(const float4*)(xr + 4) : make_float4(0, 0, 0, 0);
    float4 bb = *(const float4*)&w1[(size_t)bk * HH + bc];

    int buf = 0;
    for (int kt = 0; kt < FIN; kt += BK) {
        As[buf][ak + 0][ar] = a0.x; As[buf][ak + 1][ar] = a0.y;
        As[buf][ak + 2][ar] = a0.z; As[buf][ak + 3][ar] = a0.w;
        As[buf][ak + 4][ar] = a1.x; As[buf][ak + 5][ar] = a1.y;
        As[buf][ak + 6][ar] = a1.z; As[buf][ak + 7][ar] = a1.w;
        *(float4*)&Bs[buf][bk][bc] = bb;
        __syncthreads();
        if (kt + BK < FIN) {
            a0 = rv ? *(const float4*)(xr + kt + BK)     : make_float4(0, 0, 0, 0);
            a1 = rv ? *(const float4*)(xr + kt + BK + 4) : make_float4(0, 0, 0, 0);
            bb = *(const float4*)&w1[(size_t)(kt + BK + bk) * HH + bc];
        }
#pragma unroll
        for (int k = 0; k < BK; k++) {
            ulonglong2 A0 = *(const ulonglong2*)&As[buf][k][ty * 8];
            ulonglong2 A1 = *(const ulonglong2*)&As[buf][k][ty * 8 + 4];
            unsigned long long av[4] = {A0.x, A0.y, A1.x, A1.y};
            float4 B = *(float4*)&Bs[buf][k][tx * 4];
            unsigned long long bp[4] = {pack2(B.x, B.x), pack2(B.y, B.y),
                                        pack2(B.z, B.z), pack2(B.w, B.w)};
#pragma unroll
            for (int ip = 0; ip < 4; ip++)
#pragma unroll
                for (int j = 0; j < 4; j++) ffma2(acc[ip][j], av[ip], bp[j]);
        }
        buf ^= 1;
    }
#pragma unroll
    for (int ip = 0; ip < 4; ip++) {
        float lo[4], hi[4];
#pragma unroll
        for (int j = 0; j < 4; j++) unpack2(acc[ip][j], lo[j], hi[j]);
        int r = row0 + ty * 8 + 2 * ip;
        if (r < NN) {
            float dd = g_dis[r];
            *(float4*)&g_h[(size_t)r * HH + tx * 4] =
                make_float4(lo[0] * dd, lo[1] * dd, lo[2] * dd, lo[3] * dd);
        }
        if (r + 1 < NN) {
            float dd = g_dis[r + 1];
            *(float4*)&g_h[(size_t)(r + 1) * HH + tx * 4] =
                make_float4(hi[0] * dd, hi[1] * dd, hi[2] * dd, hi[3] * dd);
        }
    }
}

__global__ __launch_bounds__(256) void k_fat1(const float* __restrict__ x,
                                              const float* __restrict__ w1,
                                              const int* __restrict__ src,
                                              const int* __restrict__ dst,
                                              const float* __restrict__ ew,
                                              const float* __restrict__ lu) {
    int bid = blockIdx.x;
    int g = bid / 5, r = bid - g * 5;
    if (r == 0) {
        gemm1_body(x, w1, g);
    } else {
        int eb = g * 4 + (r - 1);
        if (eb >= EB1) return;
        int e = eb * 1024 + threadIdx.x * 4;
        int4   s4 = *(const int4*)&src[e];
        int4   d4 = *(const int4*)&dst[e];
        float4 w4 = *(const float4*)&ew[e];
        float4 l4 = *(const float4*)&lu[e];
        int p0 = atomicAdd(&g_cur[d4.x], 1);
        g_csr[p0] = s4.x; g_dstp[p0] = d4.x; g_ewp[p0] = w4.x; g_lup[p0] = l4.x;
        int p1 = atomicAdd(&g_cur[d4.y], 1);
        g_csr[p1] = s4.y; g_dstp[p1] = d4.y; g_ewp[p1] = w4.y; g_lup[p1] = l4.y;
        int p2 = atomicAdd(&g_cur[d4.z], 1);
        g_csr[p2] = s4.z; g_dstp[p2] = d4.z; g_ewp[p2] = w4.z; g_lup[p2] = l4.z;
        int p3 = atomicAdd(&g_cur[d4.w], 1);
        g_csr[p3] = s4.w; g_dstp[p3] = d4.w; g_ewp[p3] = w4.w; g_lup[p3] = l4.w;
        unsigned selb = g_sel[0];
        unsigned u;
        u = __float_as_uint(w4.x);
        if ((u >> 16) == selb) { atomicAdd(&g_zero[OFF_H2 + (u & 0xFFFFu)], 1u);
                                 atomicAdd(&g_zero[OFF_H2C + ((u >> 8) & 0xFFu)], 1u); }
        u = __float_as_uint(w4.y);
        if ((u >> 16) == selb) { atomicAdd(&g_zero[OFF_H2 + (u & 0xFFFFu)], 1u);
                                 atomicAdd(&g_zero[OFF_H2C + ((u >> 8) & 0xFFu)], 1u); }
        u = __float_as_uint(w4.z);
        if ((u >> 16) == selb) { atomicAdd(&g_zero[OFF_H2 + (u & 0xFFFFu)], 1u);
                                 atomicAdd(&g_zero[OFF_H2C + ((u >> 8) & 0xFFu)], 1u); }
        u = __float_as_uint(w4.w);
        if ((u >> 16) == selb) { atomicAdd(&g_zero[OFF_H2 + (u & 0xFFFFu)], 1u);
                                 atomicAdd(&g_zero[OFF_H2C + ((u >> 8) & 0xFFu)], 1u); }
    }
}

// ---- fat2: sel2 (block 0) + [gather1 + fused GEMM2] (blocks 1..3125) -------
// Each block: 8 warps x 4 iterations = 32 nodes. h1 never touches gmem.
__global__ __launch_bounds__(256) void k_fat2(const float* __restrict__ b1,
                                              const float* __restrict__ w2) {
    if (blockIdx.x == 0) {
        __shared__ unsigned c[256];
        __shared__ unsigned scg, srem;
        int t = threadIdx.x;
        c[t] = g_zero[OFF_H2C + t];
        __syncthreads();
        if (t == 0) {
            unsigned k = g_sel[1], cum = 0; int cg = 0;
            for (; cg < 256; cg++) { if (cum + c[cg] > k) break; cum += c[cg]; }
            scg = cg; srem = k - cum;
        }
        __syncthreads();
        c[t] = g_zero[OFF_H2 + scg * 256 + t];
        __syncthreads();
        if (t == 0) {
            unsigned r = srem; int b = 0;
            for (; b < 256; b++) { if (r < c[b]) break; r -= c[b]; }
            unsigned bits = (g_sel[0] << 16) | (unsigned)(scg * 256 + b);
            g_thresh = __uint_as_float(bits);
        }
        return;
    }
    __shared__ float Ws[HH * CC];       // 10 KB: w2 [k][c]
    __shared__ float sh1[8][HH];        // 2 KB: per-warp h1 staging
    int tid = threadIdx.x;
    for (int i = tid; i < HH * CC; i += 256) Ws[i] = w2[i];
    __syncthreads();
    int w = tid >> 5, lane = tid & 31;
    bool hb = lane < (CC - 32);
    int base = (blockIdx.x - 1) * 32;
    const float2* hs2 = (const float2*)g_h;
    float2 bv = ((const float2*)b1)[lane];
#pragma unroll
    for (int it = 0; it < 4; it++) {
        int n = base + it * 8 + w;                      // always < NN (3125*32)
        float2 acc = hs2[(size_t)n * 32 + lane];        // self-loop (hs[n])
        int beg = g_off[n], end = g_off[n + 1];
        int i = beg;
        for (; i + 8 <= end; i += 8) {
            int sid[8];
#pragma unroll
            for (int j = 0; j < 8; j++) sid[j] = __ldg(&g_csr[i + j]);
            float2 v[8];
#pragma unroll
            for (int j = 0; j < 8; j++) v[j] = __ldg(&hs2[(size_t)sid[j] * 32 + lane]);
#pragma unroll
            for (int j = 0; j < 8; j++) { acc.x += v[j].x; acc.y += v[j].y; }
        }
        for (; i < end; i++) {
            int s = __ldg(&g_csr[i]);
            float2 v = __ldg(&hs2[(size_t)s * 32 + lane]);
            acc.x += v.x; acc.y += v.y;
        }
        float d = g_dis[n];
        float2 o;
        o.x = fmaxf(acc.x * d + bv.x, 0.f);
        o.y = fmaxf(acc.y * d + bv.y, 0.f);
        *(float2*)&sh1[w][2 * lane] = o;
        __syncwarp();
        // fused GEMM2 row: p[n][c] = (sum_k h1[k]*W2[k][c]) * dis[n]
        float s0 = 0.f, s1 = 0.f;
#pragma unroll 8
        for (int k = 0; k < HH; k++) {
            float hv = sh1[w][k];
            s0 += hv * Ws[k * CC + lane];
            if (hb) s1 += hv * Ws[k * CC + 32 + lane];
        }
        g_p[(size_t)n * CC + lane] = s0 * d;
        if (hb) g_p[(size_t)n * CC + 32 + lane] = s1 * d;
        __syncwarp();
    }
}

// ---- gather2 + bias + bf16 y + log_softmax (warp per node) -----------------
__global__ __launch_bounds__(256) void k_gather2(const float* __restrict__ b2,
                                                 float* __restrict__ out) {
    int n = blockIdx.x * 8 + (threadIdx.x >> 5);
    if (n >= NN) return;
    int lane = threadIdx.x & 31;
    bool hb = lane < (CC - 32);
    size_t base = (size_t)n * CC;
    float va = g_p[base + lane];
    float vb = hb ? g_p[base + 32 + lane] : 0.f;
    int beg = g_off[n], end = g_off[n + 1];
    int i = beg;
    for (; i + 8 <= end; i += 8) {
        int sid[8];
#pragma unroll
        for (int j = 0; j < 8; j++) sid[j] = __ldg(&g_csr[i + j]);
        float a[8], b[8];
#pragma unroll
        for (int j = 0; j < 8; j++) {
            size_t sb = (size_t)sid[j] * CC;
            a[j] = __ldg(&g_p[sb + lane]);
            b[j] = hb ? __ldg(&g_p[sb + 32 + lane]) : 0.f;
        }
#pragma unroll
        for (int j = 0; j < 8; j++) { va += a[j]; vb += b[j]; }
    }
    for (; i < end; i++) {
        int s = __ldg(&g_csr[i]);
        size_t sb = (size_t)s * CC;
        va += __ldg(&g_p[sb + lane]);
        if (hb) vb += __ldg(&g_p[sb + 32 + lane]);
    }
    float d = g_dis[n];
    float xa = va * d + b2[lane];
    float xb = hb ? vb * d + b2[32 + lane] : 0.f;

    float sq = xa * xa + (hb ? xb * xb : 0.f);
#pragma unroll
    for (int o = 16; o; o >>= 1) sq += __shfl_xor_sync(0xffffffffu, sq, o);
    float rn = 1.f / fmaxf(sqrtf(sq), 1e-8f);
    g_y[base + lane] = __float2bfloat16(xa * rn);
    if (hb) g_y[base + 32 + lane] = __float2bfloat16(xb * rn);

    float mx = fmaxf(xa, hb ? xb : -1e30f);
#pragma unroll
    for (int o = 16; o; o >>= 1) mx = fmaxf(mx, __shfl_xor_sync(0xffffffffu, mx, o));
    float se = expf(xa - mx) + (hb ? expf(xb - mx) : 0.f);
#pragma unroll
    for (int o = 16; o; o >>= 1) se += __shfl_xor_sync(0xffffffffu, se, o);
    float ls = logf(se);
    out[base + lane] = xa - mx - ls;
    if (hb) out[base + 32 + lane] = xb - mx - ls;
}

// ---------------- edge loss: CSR order (dst rows broadcast in-warp) ---------
__device__ __forceinline__ float bf2dot(unsigned a, unsigned b) {
    float2 fa = __bfloat1622float2(*(const __nv_bfloat162*)&a);
    float2 fb = __bfloat1622float2(*(const __nv_bfloat162*)&b);
    return fa.x * fb.x + fa.y * fb.y;
}

__global__ __launch_bounds__(256) void k_loss(float* __restrict__ out,
                                              int out_size) {
    __shared__ float red_s[8];
    int pos = blockIdx.x * blockDim.x + threadIdx.x;   // EE divisible by 256
    int s = __ldg(&g_csr[pos]);
    int d = __ldg(&g_dstp[pos]);                       // ~equal across warp -> L1 bcast
    const uint4* A = (const uint4*)&g_y[(size_t)s * CC];
    const uint4* B = (const uint4*)&g_y[(size_t)d * CC];
    float dot = 0.f;
#pragma unroll
    for (int q = 0; q < 5; q++) {
        uint4 ua = __ldg(&A[q]), ub = __ldg(&B[q]);
        dot += bf2dot(ua.x, ub.x) + bf2dot(ua.y, ub.y)
             + bf2dot(ua.z, ub.z) + bf2dot(ua.w, ub.w);
    }
    float w = __ldg(&g_ewp[pos]);
    bool m = (w >= g_thresh);
    float cs = 1.f - dot;
    float lp = m ? cs : (1.f - cs);
    float le = m ? w : (1.f - w);
    float contrib = le * lp * __ldg(&g_lup[pos]);
#pragma unroll
    for (int o = 16; o; o >>= 1) contrib += __shfl_xor_sync(0xffffffffu, contrib, o);
    int lane = threadIdx.x & 31, wid = threadIdx.x >> 5;
    if (lane == 0) red_s[wid] = contrib;
    __syncthreads();
    if (wid == 0 && lane == 0) {
        float v = 0.f;
#pragma unroll
        for (int j = 0; j < 8; j++) v += red_s[j];
        atomicAdd((double*)&g_zero[OFF_LOSS], (double)v);
        __threadfence();
        unsigned old = atomicAdd(&g_zero[OFF_DONE], 1u);
        if (old == gridDim.x - 1) {
            __threadfence();
            double L = *(volatile double*)&g_zero[OFF_LOSS];
            if (out_size > NN * CC) out[out_size - 1] = (float)(L / (double)EE);
        }
    }
}

// ---------------- launch ----------------------------------------------------
extern "C" void kernel_launch(void* const* d_in, const int* in_sizes, int n_in,
                              void* d_out, int out_size) {
    const float* x  = (const float*)d_in[0];
    const int*   ei = (const int*)d_in[1];
    const float* ew = (const float*)d_in[2];
    const float* lu = (const float*)d_in[3];
    const float* w1 = (const float*)d_in[4];
    const float* b1 = (const float*)d_in[5];
    const float* w2 = (const float*)d_in[6];
    const float* b2 = (const float*)d_in[7];
    float* out = (float*)d_out;

    const int* src = ei;
    const int* dst = ei + EE;

    void* p_zero;
    cudaGetSymbolAddress(&p_zero, g_zero);
    cudaMemsetAsync(p_zero, 0, sizeof(g_zero));

    k_deg_hist<<<EE / 1024, 256>>>(dst, ew);
    k_scan_sel1<<<2, 1024>>>();
    k_fat1<<<G1B * 5, 256>>>(x, w1, src, dst, ew, lu);
    k_fat2<<<NN / 32 + 1, 256>>>(b1, w2);
    k_gather2<<<(NN + 7) / 8, 256>>>(b2, out);
    k_loss<<<EE / 256, 256>>>(out, out_size);
}

// round 11
// speedup vs baseline: 1.9442x; 1.0116x over previous
#include <cuda_runtime.h>
#include <cuda_bf16.h>
#include <math.h>

#define NN   100000
#define EE   3200000
#define FIN  512
#define HH   64
#define CC   40
#define KRANK 1600000u   // E - int(E*0.5): index into ascending sort

// ---------------- zeroed blob (single memset) -------------------------------
#define OFF_DEG    0
#define OFF_H1     (OFF_DEG + NN)           // fine hist1 (65536)
#define OFF_H1C    (OFF_H1 + 65536)         // coarse hist1 (256)
#define OFF_H2     (OFF_H1C + 256)          // fine hist2 (65536)
#define OFF_H2C    (OFF_H2 + 65536)         // coarse hist2 (256)
#define OFF_DONE   (OFF_H2C + 256)          // done counter
#define OFF_LOSS   (OFF_DONE + 2)           // double accumulator (8B aligned)
#define ZWORDS     (OFF_LOSS + 2)
__device__ __align__(8) unsigned g_zero[ZWORDS];

// ---------------- other scratch ---------------------------------------------
__device__ float          g_h[NN * HH];    // hs = (x @ w1) * dis[row]
__device__ float          g_p[NN * CC];    // ps = (h1 @ w2) * dis[row]
__device__ __nv_bfloat16  g_y[NN * CC];    // normalized logits (bf16)
__device__ float          g_dis[NN];       // (deg+1)^{-1/2}
__device__ int            g_off[NN + 1];
__device__ int            g_cur[NN];
__device__ int            g_csr[EE];       // src grouped by dst
__device__ int            g_dstp[EE];      // dst id per CSR position
__device__ float2         g_wl[EE];        // {edge weight, l_u} per CSR position
__device__ unsigned       g_sel[2];        // {fine bucket (u>>16), residual rank}
__device__ float          g_thresh;

// ---------------- f32x2 packed helpers (FFMA2) ------------------------------
__device__ __forceinline__ unsigned long long pack2(float x, float y) {
    unsigned long long r;
    asm("mov.b64 %0, {%1, %2};" : "=l"(r) : "f"(x), "f"(y));
    return r;
}
__device__ __forceinline__ void unpack2(unsigned long long v, float& x, float& y) {
    asm("mov.b64 {%0, %1}, %2;" : "=f"(x), "=f"(y) : "l"(v));
}
__device__ __forceinline__ void ffma2(unsigned long long& d,
                                      unsigned long long a, unsigned long long b) {
    asm("fma.rn.f32x2 %0, %1, %2, %0;" : "+l"(d) : "l"(a), "l"(b));
}

// ---------------- degree + fine/coarse hist1 (one E-pass, 4 edges/thread) ---
__global__ __launch_bounds__(256) void k_deg_hist(const int* __restrict__ dst,
                                                  const float* __restrict__ ew) {
    __shared__ unsigned ch[256];
    int tid = threadIdx.x;
    ch[tid] = 0;
    __syncthreads();
    int e = (blockIdx.x * 256 + tid) * 4;          // EE = 3125*1024 exactly
    int4   d4 = *(const int4*)&dst[e];
    float4 w4 = *(const float4*)&ew[e];
    int* deg = (int*)&g_zero[OFF_DEG];
    unsigned* h1 = &g_zero[OFF_H1];
    atomicAdd(&deg[d4.x], 1); atomicAdd(&deg[d4.y], 1);
    atomicAdd(&deg[d4.z], 1); atomicAdd(&deg[d4.w], 1);
    unsigned u;
    u = __float_as_uint(w4.x); atomicAdd(&h1[u >> 16], 1u); atomicAdd(&ch[u >> 24], 1u);
    u = __float_as_uint(w4.y); atomicAdd(&h1[u >> 16], 1u); atomicAdd(&ch[u >> 24], 1u);
    u = __float_as_uint(w4.z); atomicAdd(&h1[u >> 16], 1u); atomicAdd(&ch[u >> 24], 1u);
    u = __float_as_uint(w4.w); atomicAdd(&h1[u >> 16], 1u); atomicAdd(&ch[u >> 24], 1u);
    __syncthreads();
    if (ch[tid]) atomicAdd(&g_zero[OFF_H1C + tid], ch[tid]);
}

// ---------------- scan (block 0) + sel1 (block 1) ---------------------------
__global__ __launch_bounds__(1024) void k_scan_sel1() {
    if (blockIdx.x == 0) {
        const int CH2 = 100;                       // 1000 active threads
        int t = threadIdx.x;
        int start = t * CH2;
        const int* deg = (const int*)&g_zero[OFF_DEG];
        int s = 0;
        if (start < NN) {
#pragma unroll
            for (int q = 0; q < 25; q++) {
                int4 dv = *(const int4*)&deg[start + q * 4];
                s += dv.x + dv.y + dv.z + dv.w;
            }
        }
        __shared__ int wsum[32];
        int lane = t & 31, wid = t >> 5;
        int v = s;
#pragma unroll
        for (int o = 1; o < 32; o <<= 1) {
            int u = __shfl_up_sync(0xffffffffu, v, o);
            if (lane >= o) v += u;
        }
        if (lane == 31) wsum[wid] = v;
        __syncthreads();
        if (wid == 0) {
            int w = wsum[lane];
#pragma unroll
            for (int o = 1; o < 32; o <<= 1) {
                int u = __shfl_up_sync(0xffffffffu, w, o);
                if (lane >= o) w += u;
            }
            wsum[lane] = w;
        }
        __syncthreads();
        int base = v - s + (wid > 0 ? wsum[wid - 1] : 0);
        if (start < NN) {
            int run = base;
#pragma unroll
            for (int q = 0; q < 25; q++) {
                int idx = start + q * 4;
                int4 dv = *(const int4*)&deg[idx];
                int4 off; float4 ds;
                off.x = run; ds.x = rsqrtf((float)dv.x + 1.f); run += dv.x;
                off.y = run; ds.y = rsqrtf((float)dv.y + 1.f); run += dv.y;
                off.z = run; ds.z = rsqrtf((float)dv.z + 1.f); run += dv.z;
                off.w = run; ds.w = rsqrtf((float)dv.w + 1.f); run += dv.w;
                *(int4*)&g_off[idx]  = off;
                *(int4*)&g_cur[idx]  = off;
                *(float4*)&g_dis[idx] = ds;
            }
            if (start + CH2 >= NN) g_off[NN] = run;
        }
    } else {
        __shared__ unsigned c[256];
        __shared__ unsigned scg, srem;
        int t = threadIdx.x;
        if (t < 256) c[t] = g_zero[OFF_H1C + t];
        __syncthreads();
        if (t == 0) {
            unsigned k = KRANK, cum = 0; int cg = 0;
            for (; cg < 256; cg++) { if (cum + c[cg] > k) break; cum += c[cg]; }
            scg = cg; srem = k - cum;
        }
        __syncthreads();
        if (t < 256) c[t] = g_zero[OFF_H1 + scg * 256 + t];
        __syncthreads();
        if (t == 0) {
            unsigned r = srem; int b = 0;
            for (; b < 256; b++) { if (r < c[b]) break; r -= c[b]; }
            g_sel[0] = scg * 256 + b;
            g_sel[1] = r;
        }
    }
}

// ---------------- fat1: gemm1 (bid%5==0) interleaved with fill+hist2 --------
#define BM 128
#define BK 16
#define G1B 782                               // ceil(NN/128)
#define EB1 3125                              // edge blocks (1024 edges each)

__device__ __forceinline__ void gemm1_body(const float* __restrict__ x,
                                           const float* __restrict__ w1, int blk) {
    __shared__ float As[2][BK][BM];
    __shared__ float Bs[2][BK][HH];
    int tid = threadIdx.x;
    int row0 = blk * BM;

    int ar = tid >> 1, ak = (tid & 1) * 8;
    int bk = tid >> 4, bc = (tid & 15) * 4;
    int ty = tid >> 4, tx = tid & 15;
    const bool rv = (row0 + ar) < NN;
    const float* xr = x + (size_t)(row0 + ar) * FIN + ak;

    unsigned long long acc[4][4];
#pragma unroll
    for (int i = 0; i < 4; i++)
#pragma unroll
        for (int j = 0; j < 4; j++) acc[i][j] = 0ull;

    float4 a0 = rv ? *(const float4*)(xr + 0) : make_float4(0, 0, 0, 0);
    float4 a1 = rv ? *(const float4*)(xr + 4) : make_float4(0, 0, 0, 0);
    float4 bb = *(const float4*)&w1[(size_t)bk * HH + bc];

    int buf = 0;
    for (int kt = 0; kt < FIN; kt += BK) {
        As[buf][ak + 0][ar] = a0.x; As[buf][ak + 1][ar] = a0.y;
        As[buf][ak + 2][ar] = a0.z; As[buf][ak + 3][ar] = a0.w;
        As[buf][ak + 4][ar] = a1.x; As[buf][ak + 5][ar] = a1.y;
        As[buf][ak + 6][ar] = a1.z; As[buf][ak + 7][ar] = a1.w;
        *(float4*)&Bs[buf][bk][bc] = bb;
        __syncthreads();
        if (kt + BK < FIN) {
            a0 = rv ? *(const float4*)(xr + kt + BK)     : make_float4(0, 0, 0, 0);
            a1 = rv ? *(const float4*)(xr + kt + BK + 4) : make_float4(0, 0, 0, 0);
            bb = *(const float4*)&w1[(size_t)(kt + BK + bk) * HH + bc];
        }
#pragma unroll
        for (int k = 0; k < BK; k++) {
            ulonglong2 A0 = *(const ulonglong2*)&As[buf][k][ty * 8];
            ulonglong2 A1 = *(const ulonglong2*)&As[buf][k][ty * 8 + 4];
            unsigned long long av[4] = {A0.x, A0.y, A1.x, A1.y};
            float4 B = *(float4*)&Bs[buf][k][tx * 4];
            unsigned long long bp[4] = {pack2(B.x, B.x), pack2(B.y, B.y),
                                        pack2(B.z, B.z), pack2(B.w, B.w)};
#pragma unroll
            for (int ip = 0; ip < 4; ip++)
#pragma unroll
                for (int j = 0; j < 4; j++) ffma2(acc[ip][j], av[ip], bp[j]);
        }
        buf ^= 1;
    }
#pragma unroll
    for (int ip = 0; ip < 4; ip++) {
        float lo[4], hi[4];
#pragma unroll
        for (int j = 0; j < 4; j++) unpack2(acc[ip][j], lo[j], hi[j]);
        int r = row0 + ty * 8 + 2 * ip;
        if (r < NN) {
            float dd = g_dis[r];
            *(float4*)&g_h[(size_t)r * HH + tx * 4] =
                make_float4(lo[0] * dd, lo[1] * dd, lo[2] * dd, lo[3] * dd);
        }
        if (r + 1 < NN) {
            float dd = g_dis[r + 1];
            *(float4*)&g_h[(size_t)(r + 1) * HH + tx * 4] =
                make_float4(hi[0] * dd, hi[1] * dd, hi[2] * dd, hi[3] * dd);
        }
    }
}

__global__ __launch_bounds__(256) void k_fat1(const float* __restrict__ x,
                                              const float* __restrict__ w1,
                                              const int* __restrict__ src,
                                              const int* __restrict__ dst,
                                              const float* __restrict__ ew,
                                              const float* __restrict__ lu) {
    int bid = blockIdx.x;
    int g = bid / 5, r = bid - g * 5;
    if (r == 0) {
        gemm1_body(x, w1, g);
    } else {
        int eb = g * 4 + (r - 1);
        if (eb >= EB1) return;
        int e = eb * 1024 + threadIdx.x * 4;
        int4   s4 = *(const int4*)&src[e];
        int4   d4 = *(const int4*)&dst[e];
        float4 w4 = *(const float4*)&ew[e];
        float4 l4 = *(const float4*)&lu[e];
        int p0 = atomicAdd(&g_cur[d4.x], 1);
        g_csr[p0] = s4.x; g_dstp[p0] = d4.x; g_wl[p0] = make_float2(w4.x, l4.x);
        int p1 = atomicAdd(&g_cur[d4.y], 1);
        g_csr[p1] = s4.y; g_dstp[p1] = d4.y; g_wl[p1] = make_float2(w4.y, l4.y);
        int p2 = atomicAdd(&g_cur[d4.z], 1);
        g_csr[p2] = s4.z; g_dstp[p2] = d4.z; g_wl[p2] = make_float2(w4.z, l4.z);
        int p3 = atomicAdd(&g_cur[d4.w], 1);
        g_csr[p3] = s4.w; g_dstp[p3] = d4.w; g_wl[p3] = make_float2(w4.w, l4.w);
        unsigned selb = g_sel[0];
        unsigned u;
        u = __float_as_uint(w4.x);
        if ((u >> 16) == selb) { atomicAdd(&g_zero[OFF_H2 + (u & 0xFFFFu)], 1u);
                                 atomicAdd(&g_zero[OFF_H2C + ((u >> 8) & 0xFFu)], 1u); }
        u = __float_as_uint(w4.y);
        if ((u >> 16) == selb) { atomicAdd(&g_zero[OFF_H2 + (u & 0xFFFFu)], 1u);
                                 atomicAdd(&g_zero[OFF_H2C + ((u >> 8) & 0xFFu)], 1u); }
        u = __float_as_uint(w4.z);
        if ((u >> 16) == selb) { atomicAdd(&g_zero[OFF_H2 + (u & 0xFFFFu)], 1u);
                                 atomicAdd(&g_zero[OFF_H2C + ((u >> 8) & 0xFFu)], 1u); }
        u = __float_as_uint(w4.w);
        if ((u >> 16) == selb) { atomicAdd(&g_zero[OFF_H2 + (u & 0xFFFFu)], 1u);
                                 atomicAdd(&g_zero[OFF_H2C + ((u >> 8) & 0xFFu)], 1u); }
    }
}

// ---- fat2: sel2 (block 0) + [gather1 + fused GEMM2] (blocks 1..3125) -------
// GEMM2 uses transposed padded Wt (float4 LDS, phase-conflict-free).
__global__ __launch_bounds__(256) void k_fat2(const float* __restrict__ b1,
                                              const float* __restrict__ w2) {
    if (blockIdx.x == 0) {
        __shared__ unsigned c[256];
        __shared__ unsigned scg, srem;
        int t = threadIdx.x;
        c[t] = g_zero[OFF_H2C + t];
        __syncthreads();
        if (t == 0) {
            unsigned k = g_sel[1], cum = 0; int cg = 0;
            for (; cg < 256; cg++) { if (cum + c[cg] > k) break; cum += c[cg]; }
            scg = cg; srem = k - cum;
        }
        __syncthreads();
        c[t] = g_zero[OFF_H2 + scg * 256 + t];
        __syncthreads();
        if (t == 0) {
            unsigned r = srem; int b = 0;
            for (; b < 256; b++) { if (r < c[b]) break; r -= c[b]; }
            unsigned bits = (g_sel[0] << 16) | (unsigned)(scg * 256 + b);
            g_thresh = __uint_as_float(bits);
        }
        return;
    }
    __shared__ float Wt[CC * 68];       // Wt[c*68+k] = w2[k][c]; 10880 B
    __shared__ float sh1[8][HH];        // per-warp h1 staging
    int tid = threadIdx.x;
    for (int i = tid; i < HH * CC; i += 256) {
        int k = i / CC, c = i - k * CC;              // coalesced global read
        Wt[c * 68 + k] = w2[i];
    }
    __syncthreads();
    int w = tid >> 5, lane = tid & 31;
    bool hb = lane < (CC - 32);
    int base = (blockIdx.x - 1) * 32;
    const float2* hs2 = (const float2*)g_h;
    float2 bv = ((const float2*)b1)[lane];
    const float* wrow0 = &Wt[lane * 68];
    const float* wrow1 = &Wt[(lane + 32) * 68];      // used only when hb
#pragma unroll
    for (int it = 0; it < 4; it++) {
        int n = base + it * 8 + w;                      // always < NN (3125*32)
        float2 acc = hs2[(size_t)n * 32 + lane];        // self-loop (hs[n])
        int beg = g_off[n], end = g_off[n + 1];
        int i = beg;
        for (; i + 8 <= end; i += 8) {
            int sid[8];
#pragma unroll
            for (int j = 0; j < 8; j++) sid[j] = __ldg(&g_csr[i + j]);
            float2 v[8];
#pragma unroll
            for (int j = 0; j < 8; j++) v[j] = __ldg(&hs2[(size_t)sid[j] * 32 + lane]);
#pragma unroll
            for (int j = 0; j < 8; j++) { acc.x += v[j].x; acc.y += v[j].y; }
        }
        for (; i < end; i++) {
            int s = __ldg(&g_csr[i]);
            float2 v = __ldg(&hs2[(size_t)s * 32 + lane]);
            acc.x += v.x; acc.y += v.y;
        }
        float d = g_dis[n];
        float2 o;
        o.x = fmaxf(acc.x * d + bv.x, 0.f);
        o.y = fmaxf(acc.y * d + bv.y, 0.f);
        *(float2*)&sh1[w][2 * lane] = o;
        __syncwarp();
        // fused GEMM2 row: p[n][c] = (sum_k h1[k]*W2[k][c]) * dis[n]
        float s0 = 0.f, s1 = 0.f;
#pragma unroll
        for (int k = 0; k < HH; k += 4) {
            float4 hv = *(const float4*)&sh1[w][k];     // broadcast
            float4 wa = *(const float4*)&wrow0[k];
            s0 += hv.x * wa.x + hv.y * wa.y + hv.z * wa.z + hv.w * wa.w;
            if (hb) {
                float4 wb = *(const float4*)&wrow1[k];
                s1 += hv.x * wb.x + hv.y * wb.y + hv.z * wb.z + hv.w * wb.w;
            }
        }
        g_p[(size_t)n * CC + lane] = s0 * d;
        if (hb) g_p[(size_t)n * CC + 32 + lane] = s1 * d;
        __syncwarp();
    }
}

// ---- gather2 + bias + bf16 y + log_softmax (warp per node) -----------------
__global__ __launch_bounds__(256) void k_gather2(const float* __restrict__ b2,
                                                 float* __restrict__ out) {
    int n = blockIdx.x * 8 + (threadIdx.x >> 5);
    if (n >= NN) return;
    int lane = threadIdx.x & 31;
    bool hb = lane < (CC - 32);
    size_t base = (size_t)n * CC;
    float va = g_p[base + lane];
    float vb = hb ? g_p[base + 32 + lane] : 0.f;
    int beg = g_off[n], end = g_off[n + 1];
    int i = beg;
    for (; i + 8 <= end; i += 8) {
        int sid[8];
#pragma unroll
        for (int j = 0; j < 8; j++) sid[j] = __ldg(&g_csr[i + j]);
        float a[8], b[8];
#pragma unroll
        for (int j = 0; j < 8; j++) {
            size_t sb = (size_t)sid[j] * CC;
            a[j] = __ldg(&g_p[sb + lane]);
            b[j] = hb ? __ldg(&g_p[sb + 32 + lane]) : 0.f;
        }
#pragma unroll
        for (int j = 0; j < 8; j++) { va += a[j]; vb += b[j]; }
    }
    for (; i < end; i++) {
        int s = __ldg(&g_csr[i]);
        size_t sb = (size_t)s * CC;
        va += __ldg(&g_p[sb + lane]);
        if (hb) vb += __ldg(&g_p[sb + 32 + lane]);
    }
    float d = g_dis[n];
    float xa = va * d + b2[lane];
    float xb = hb ? vb * d + b2[32 + lane] : 0.f;

    float sq = xa * xa + (hb ? xb * xb : 0.f);
#pragma unroll
    for (int o = 16; o; o >>= 1) sq += __shfl_xor_sync(0xffffffffu, sq, o);
    float rn = 1.f / fmaxf(sqrtf(sq), 1e-8f);
    g_y[base + lane] = __float2bfloat16(xa * rn);
    if (hb) g_y[base + 32 + lane] = __float2bfloat16(xb * rn);

    float mx = fmaxf(xa, hb ? xb : -1e30f);
#pragma unroll
    for (int o = 16; o; o >>= 1) mx = fmaxf(mx, __shfl_xor_sync(0xffffffffu, mx, o));
    float se = expf(xa - mx) + (hb ? expf(xb - mx) : 0.f);
#pragma unroll
    for (int o = 16; o; o >>= 1) se += __shfl_xor_sync(0xffffffffu, se, o);
    float ls = logf(se);
    out[base + lane] = xa - mx - ls;
    if (hb) out[base + 32 + lane] = xb - mx - ls;
}

// ---------------- edge loss: CSR chunks, ONE atomic per block ---------------
#define LCH 2720
#define LGB ((EE + LCH - 1) / LCH)            // 1177 blocks

__device__ __forceinline__ float bf2dot(unsigned a, unsigned b) {
    float2 fa = __bfloat1622float2(*(const __nv_bfloat162*)&a);
    float2 fb = __bfloat1622float2(*(const __nv_bfloat162*)&b);
    return fa.x * fb.x + fa.y * fb.y;
}

__global__ __launch_bounds__(256) void k_loss(float* __restrict__ out,
                                              int out_size) {
    __shared__ float red_s[8];
    int base = blockIdx.x * LCH;
    int stop = min(base + LCH, EE);
    float th = g_thresh;
    float acc = 0.f;
    for (int pos = base + threadIdx.x; pos < stop; pos += 256) {
        int s = __ldg(&g_csr[pos]);
        int d = __ldg(&g_dstp[pos]);                   // ~uniform in warp -> L1 bcast
        const uint4* A = (const uint4*)&g_y[(size_t)s * CC];
        const uint4* B = (const uint4*)&g_y[(size_t)d * CC];
        float dot = 0.f;
#pragma unroll
        for (int q = 0; q < 5; q++) {
            uint4 ua = __ldg(&A[q]), ub = __ldg(&B[q]);
            dot += bf2dot(ua.x, ub.x) + bf2dot(ua.y, ub.y)
                 + bf2dot(ua.z, ub.z) + bf2dot(ua.w, ub.w);
        }
        float2 wl = __ldg(&g_wl[pos]);
        bool m = (wl.x >= th);
        float cs = 1.f - dot;
        float lp = m ? cs : (1.f - cs);
        float le = m ? wl.x : (1.f - wl.x);
        acc += le * lp * wl.y;
    }
#pragma unroll
    for (int o = 16; o; o >>= 1) acc += __shfl_xor_sync(0xffffffffu, acc, o);
    int lane = threadIdx.x & 31, wid = threadIdx.x >> 5;
    if (lane == 0) red_s[wid] = acc;
    __syncthreads();
    if (wid == 0 && lane == 0) {
        float v = 0.f;
#pragma unroll
        for (int j = 0; j < 8; j++) v += red_s[j];
        atomicAdd((double*)&g_zero[OFF_LOSS], (double)v);
        __threadfence();
        unsigned old = atomicAdd(&g_zero[OFF_DONE], 1u);
        if (old == gridDim.x - 1) {
            __threadfence();
            double L = *(volatile double*)&g_zero[OFF_LOSS];
            if (out_size > NN * CC) out[out_size - 1] = (float)(L / (double)EE);
        }
    }
}

// ---------------- launch ----------------------------------------------------
extern "C" void kernel_launch(void* const* d_in, const int* in_sizes, int n_in,
                              void* d_out, int out_size) {
    const float* x  = (const float*)d_in[0];
    const int*   ei = (const int*)d_in[1];
    const float* ew = (const float*)d_in[2];
    const float* lu = (const float*)d_in[3];
    const float* w1 = (const float*)d_in[4];
    const float* b1 = (const float*)d_in[5];
    const float* w2 = (const float*)d_in[6];
    const float* b2 = (const float*)d_in[7];
    float* out = (float*)d_out;

    const int* src = ei;
    const int* dst = ei + EE;

    void* p_zero;
    cudaGetSymbolAddress(&p_zero, g_zero);
    cudaMemsetAsync(p_zero, 0, sizeof(g_zero));

    k_deg_hist<<<EE / 1024, 256>>>(dst, ew);
    k_scan_sel1<<<2, 1024>>>();
    k_fat1<<<G1B * 5, 256>>>(x, w1, src, dst, ew, lu);
    k_fat2<<<NN / 32 + 1, 256>>>(b1, w2);
    k_gather2<<<(NN + 7) / 8, 256>>>(b2, out);
    k_loss<<<LGB, 256>>>(out, out_size);
}